// round 3
// baseline (speedup 1.0000x reference)
#include <cuda_runtime.h>
#include <math.h>

// Problem constants (fixed by the dataset)
#define NMAX 100000
#define EMAX 3200000
#define HID  32
#define NC   30

// ---------------- scratch (__device__ globals; no allocation) ----------------
__device__ int    g_cnt[NMAX];
__device__ int    g_rowstart[NMAX + 1];
__device__ int    g_cursor[NMAX];
__device__ int    g_csr[EMAX];
__device__ float  g_dinv[NMAX];
__device__ float  g_h1s[NMAX * 32];    // dinv[n] * (x @ W1)[n, :]
__device__ float  g_hrelu[NMAX * 32];  // relu layer-1 output
__device__ float  g_zs[NMAX * 32];     // dinv[n] * (hrelu @ W2)[n, :] (padded, lanes>=30 zero)
__device__ float  g_fx[NMAX * 32];     // softmax FX padded to 32 (lanes>=30 zero)
__device__ int    g_bsum[256];
__device__ int    g_boff[256];
__device__ double g_colsum[32];
__device__ double g_mse;

// ---------------- small utility kernels ----------------
__global__ void k_zero(int N) {
    int i = blockIdx.x * blockDim.x + threadIdx.x;
    int stride = gridDim.x * blockDim.x;
    for (int j = i; j < N; j += stride) g_cnt[j] = 0;
    if (blockIdx.x == 0 && threadIdx.x < 32) g_colsum[threadIdx.x] = 0.0;
    if (blockIdx.x == 0 && threadIdx.x == 0) g_mse = 0.0;
}

__global__ void k_hist(const int* __restrict__ ei, int E) {
    int i = blockIdx.x * blockDim.x + threadIdx.x;
    int stride = gridDim.x * blockDim.x;
    for (int e = i; e < E; e += stride) {
        int d = ei[E + e];
        atomicAdd(&g_cnt[d], 1);
    }
}

// block partial sums over 1024-chunks
__global__ void k_scan1(int N) {
    __shared__ int sh[1024];
    int t = threadIdx.x;
    int i = blockIdx.x * 1024 + t;
    int v = (i < N) ? g_cnt[i] : 0;
    sh[t] = v;
    __syncthreads();
    for (int off = 512; off > 0; off >>= 1) {
        if (t < off) sh[t] += sh[t + off];
        __syncthreads();
    }
    if (t == 0) g_bsum[blockIdx.x] = sh[0];
}

__global__ void k_scan2(int NB) {
    if (threadIdx.x == 0) {
        int run = 0;
        for (int b = 0; b < NB; b++) { g_boff[b] = run; run += g_bsum[b]; }
    }
}

__global__ void k_scan3(int N, int E) {
    __shared__ int sh[1024];
    int t = threadIdx.x;
    int i = blockIdx.x * 1024 + t;
    int v = (i < N) ? g_cnt[i] : 0;
    sh[t] = v;
    __syncthreads();
    // Hillis-Steele inclusive scan
    for (int off = 1; off < 1024; off <<= 1) {
        int a = (t >= off) ? sh[t - off] : 0;
        __syncthreads();
        sh[t] += a;
        __syncthreads();
    }
    if (i < N) {
        int incl = sh[t];
        int base = g_boff[blockIdx.x];
        int rs = base + incl - v;
        g_rowstart[i] = rs;
        g_cursor[i] = rs;
        g_dinv[i] = rsqrtf((float)(v + 1));  // deg = in-degree + self-loop
        if (i == N - 1) g_rowstart[N] = base + incl;
    }
}

__global__ void k_scatter(const int* __restrict__ ei, int E) {
    int i = blockIdx.x * blockDim.x + threadIdx.x;
    int stride = gridDim.x * blockDim.x;
    for (int e = i; e < E; e += stride) {
        int s = ei[e];
        int d = ei[E + e];
        int p = atomicAdd(&g_cursor[d], 1);
        g_csr[p] = s;
    }
}

// ---------------- GEMM1: h1s = dinv * (x @ W1), warp per node ----------------
__global__ void __launch_bounds__(256) k_gemm1(const float* __restrict__ x,
                                               const float* __restrict__ W1, int N) {
    __shared__ float Ws[128 * 32];
    for (int i = threadIdx.x; i < 128 * 32; i += blockDim.x) Ws[i] = W1[i];
    __syncthreads();
    int lane = threadIdx.x & 31;
    int warp = (blockIdx.x * blockDim.x + threadIdx.x) >> 5;
    int nwarps = (gridDim.x * blockDim.x) >> 5;
    for (int n = warp; n < N; n += nwarps) {
        const float* xr = x + (size_t)n * 128;
        float x0 = xr[lane], x1 = xr[32 + lane], x2 = xr[64 + lane], x3 = xr[96 + lane];
        float acc = 0.f;
#pragma unroll
        for (int m = 0; m < 32; m++) {
            acc = fmaf(__shfl_sync(0xffffffffu, x0, m), Ws[m * 32 + lane], acc);
            acc = fmaf(__shfl_sync(0xffffffffu, x1, m), Ws[(32 + m) * 32 + lane], acc);
            acc = fmaf(__shfl_sync(0xffffffffu, x2, m), Ws[(64 + m) * 32 + lane], acc);
            acc = fmaf(__shfl_sync(0xffffffffu, x3, m), Ws[(96 + m) * 32 + lane], acc);
        }
        g_h1s[n * 32 + lane] = acc * g_dinv[n];
    }
}

// ---------------- Aggregation layer 1 + bias + relu ----------------
__global__ void __launch_bounds__(256) k_agg1(const float* __restrict__ b1, int N) {
    int lane = threadIdx.x & 31;
    int warp = (blockIdx.x * blockDim.x + threadIdx.x) >> 5;
    int nwarps = (gridDim.x * blockDim.x) >> 5;
    float bias = b1[lane];
    for (int n = warp; n < N; n += nwarps) {
        int r0 = g_rowstart[n], r1 = g_rowstart[n + 1];
        float acc = g_h1s[n * 32 + lane];  // self-loop term
        for (int j = r0; j < r1; j++) {
            int s = __ldg(&g_csr[j]);
            acc += g_h1s[s * 32 + lane];
        }
        g_hrelu[n * 32 + lane] = fmaxf(g_dinv[n] * acc + bias, 0.f);
    }
}

// ---------------- GEMM2: zs = dinv * (hrelu @ W2), padded to 32 cols ----------------
__global__ void __launch_bounds__(256) k_gemm2(const float* __restrict__ W2, int N) {
    __shared__ float Ws[32 * 32];  // padded: cols >= 30 are zero
    for (int i = threadIdx.x; i < 32 * 32; i += blockDim.x) {
        int k = i >> 5, c = i & 31;
        Ws[i] = (c < NC) ? W2[k * NC + c] : 0.f;
    }
    __syncthreads();
    int lane = threadIdx.x & 31;
    int warp = (blockIdx.x * blockDim.x + threadIdx.x) >> 5;
    int nwarps = (gridDim.x * blockDim.x) >> 5;
    for (int n = warp; n < N; n += nwarps) {
        float hv = g_hrelu[n * 32 + lane];
        float acc = 0.f;
#pragma unroll
        for (int k = 0; k < 32; k++)
            acc = fmaf(__shfl_sync(0xffffffffu, hv, k), Ws[k * 32 + lane], acc);
        g_zs[n * 32 + lane] = (lane < NC) ? acc * g_dinv[n] : 0.f;
    }
}

// ---------------- Aggregation layer 2 + bias + softmax + NFX column sums ----------------
__global__ void __launch_bounds__(256) k_agg2(const float* __restrict__ b2,
                                              float* __restrict__ out, int N) {
    __shared__ float scs[32];
    int lane = threadIdx.x & 31;
    if (threadIdx.x < 32) scs[threadIdx.x] = 0.f;
    __syncthreads();
    int warp = (blockIdx.x * blockDim.x + threadIdx.x) >> 5;
    int nwarps = (gridDim.x * blockDim.x) >> 5;
    float bias = (lane < NC) ? b2[lane] : 0.f;
    float nfacc = 0.f;  // per-thread accumulator for column-sum of log(1-FX^2)
    for (int n = warp; n < N; n += nwarps) {
        int r0 = g_rowstart[n], r1 = g_rowstart[n + 1];
        float acc = g_zs[n * 32 + lane];  // self-loop
        for (int j = r0; j < r1; j++) {
            int s = __ldg(&g_csr[j]);
            acc += g_zs[s * 32 + lane];
        }
        float logit = (lane < NC) ? (g_dinv[n] * acc + bias) : -1e30f;
        // warp softmax over 30 active lanes
        float m = logit;
#pragma unroll
        for (int o = 16; o > 0; o >>= 1) m = fmaxf(m, __shfl_xor_sync(0xffffffffu, m, o));
        float p = (lane < NC) ? expf(logit - m) : 0.f;
        float s = p;
#pragma unroll
        for (int o = 16; o > 0; o >>= 1) s += __shfl_xor_sync(0xffffffffu, s, o);
        float fx = p / s;
        g_fx[n * 32 + lane] = fx;  // lanes >= 30 store 0
        if (lane < NC) {
            out[(size_t)n * NC + lane] = fx;
            nfacc += logf(1.f - fx * fx);
        }
    }
    atomicAdd(&scs[lane], nfacc);
    __syncthreads();
    if (threadIdx.x < 32) {
        float v = scs[threadIdx.x];
        if (v != 0.f) atomicAdd(&g_colsum[threadIdx.x], (double)v);
    }
}

// ---------------- FF = <FX[src], FX[dst]>, MSE vs edge_pred ----------------
__global__ void __launch_bounds__(256) k_ff(const int* __restrict__ ei,
                                            const float* __restrict__ ep, int E) {
    __shared__ float red[256];
    int lane = threadIdx.x & 31;
    int warp = (blockIdx.x * blockDim.x + threadIdx.x) >> 5;
    int nwarps = (gridDim.x * blockDim.x) >> 5;
    float acc = 0.f;
    for (int base = warp * 32; base < E; base += nwarps * 32) {
        int e = base + lane;
        bool valid = (e < E);
        int sl = valid ? ei[e] : 0;
        int dl = valid ? ei[E + e] : 0;
        float pl = valid ? ep[e] : 0.f;
        int cnt = min(32, E - base);
        for (int i = 0; i < cnt; i++) {
            int s = __shfl_sync(0xffffffffu, sl, i);
            int d = __shfl_sync(0xffffffffu, dl, i);
            float v = g_fx[s * 32 + lane] * g_fx[d * 32 + lane];  // lanes>=30 contribute 0
#pragma unroll
            for (int o = 16; o > 0; o >>= 1) v += __shfl_xor_sync(0xffffffffu, v, o);
            if (lane == i) {
                float diff = v - pl;
                acc += diff * diff;
            }
        }
    }
    red[threadIdx.x] = acc;
    __syncthreads();
    for (int off = 128; off > 0; off >>= 1) {
        if (threadIdx.x < off) red[threadIdx.x] += red[threadIdx.x + off];
        __syncthreads();
    }
    if (threadIdx.x == 0) atomicAdd(&g_mse, (double)red[0]);
}

// ---------------- final loss ----------------
__global__ void k_finish(float* __restrict__ out, int N, int E) {
    if (threadIdx.x == 0 && blockIdx.x == 0) {
        double preg = 0.0;
        for (int c = 0; c < NC; c++) {
            double S = g_colsum[c];
            preg -= log(1.0001 - exp(S));
        }
        double loss = g_mse / (double)E + 0.01 * preg;
        out[(size_t)N * NC] = (float)loss;
    }
}

// ---------------- launch ----------------
extern "C" void kernel_launch(void* const* d_in, const int* in_sizes, int n_in,
                              void* d_out, int out_size) {
    const float* x  = (const float*)d_in[0];
    const int*   ei = (const int*)d_in[1];     // int32: JAX x64 disabled
    const float* ep = (const float*)d_in[2];
    const float* W1 = (const float*)d_in[3];
    const float* b1 = (const float*)d_in[4];
    const float* W2 = (const float*)d_in[5];
    const float* b2 = (const float*)d_in[6];
    float* out = (float*)d_out;

    int N = in_sizes[0] / 128;   // 100000
    int E = in_sizes[2];         // 3200000
    int NB = (N + 1023) / 1024;

    k_zero<<<256, 256>>>(N);
    k_hist<<<1024, 256>>>(ei, E);
    k_scan1<<<NB, 1024>>>(N);
    k_scan2<<<1, 32>>>(NB);
    k_scan3<<<NB, 1024>>>(N, E);
    k_scatter<<<1024, 256>>>(ei, E);
    k_gemm1<<<1024, 256>>>(x, W1, N);
    k_agg1<<<512, 256>>>(b1, N);
    k_gemm2<<<512, 256>>>(W2, N);
    k_agg2<<<512, 256>>>(b2, out, N);
    k_ff<<<1024, 256>>>(ei, ep, E);
    k_finish<<<1, 32>>>(out, N, E);
}

// round 5
// speedup vs baseline: 1.1255x; 1.1255x over previous
#include <cuda_runtime.h>
#include <cuda_bf16.h>
#include <math.h>

#define NMAX 100000
#define EMAX 3200000
#define NC   30

// ---------------- scratch ----------------
__device__ int    g_cnt[NMAX];
__device__ int    g_rowstart[NMAX + 1];
__device__ int    g_cursor[NMAX];
__device__ int    g_csr[EMAX];
__device__ float  g_dinv[NMAX];
__device__ float  g_h1s[NMAX * 32];      // dinv[n] * (x @ W1)[n,:]
__device__ float  g_zs[NMAX * 32];       // dinv[n] * (relu(...) @ W2)[n,:], padded
__device__ __nv_bfloat162 g_fxh[NMAX * 16];  // FX rows in bf16 (for k_ff only)
__device__ int    g_bsum[128];
__device__ double g_colsum[32];
__device__ double g_mse;

// ---------------- init ----------------
__global__ void k_zero(int N) {
    int i = blockIdx.x * blockDim.x + threadIdx.x;
    int stride = gridDim.x * blockDim.x;
    for (int j = i; j < N; j += stride) g_cnt[j] = 0;
    if (blockIdx.x == 0 && threadIdx.x < 32) g_colsum[threadIdx.x] = 0.0;
    if (blockIdx.x == 0 && threadIdx.x == 0) g_mse = 0.0;
}

// ---------------- degree histogram (int4 edge loads) ----------------
__global__ void k_hist(const int* __restrict__ ei, int E) {
    int i = blockIdx.x * blockDim.x + threadIdx.x;
    int stride = gridDim.x * blockDim.x;
    int nv = E >> 2;
    const int4* d4p = (const int4*)(ei + E);
    for (int v = i; v < nv; v += stride) {
        int4 d = d4p[v];
        atomicAdd(&g_cnt[d.x], 1);
        atomicAdd(&g_cnt[d.y], 1);
        atomicAdd(&g_cnt[d.z], 1);
        atomicAdd(&g_cnt[d.w], 1);
    }
}

// block partial sums over 1024-chunks
__global__ void k_scan1(int N) {
    __shared__ int sh[1024];
    int t = threadIdx.x;
    int i = blockIdx.x * 1024 + t;
    int v = (i < N) ? g_cnt[i] : 0;
    sh[t] = v;
    __syncthreads();
    for (int off = 512; off > 0; off >>= 1) {
        if (t < off) sh[t] += sh[t + off];
        __syncthreads();
    }
    if (t == 0) g_bsum[blockIdx.x] = sh[0];
}

// per-block scan; block prefix over g_bsum computed inline by warp 0
__global__ void k_scan3(int N) {
    __shared__ int sh[1024];
    __shared__ int sbase;
    int t = threadIdx.x;
    int i = blockIdx.x * 1024 + t;
    int v = (i < N) ? g_cnt[i] : 0;
    sh[t] = v;
    if (t < 32) {
        int ssum = 0;
        for (int b = t; b < blockIdx.x; b += 32) ssum += g_bsum[b];
#pragma unroll
        for (int o = 16; o > 0; o >>= 1) ssum += __shfl_xor_sync(0xffffffffu, ssum, o);
        if (t == 0) sbase = ssum;
    }
    __syncthreads();
    for (int off = 1; off < 1024; off <<= 1) {
        int a = (t >= off) ? sh[t - off] : 0;
        __syncthreads();
        sh[t] += a;
        __syncthreads();
    }
    if (i < N) {
        int incl = sh[t];
        int base = sbase;
        int rs = base + incl - v;
        g_rowstart[i] = rs;
        g_cursor[i] = rs;
        g_dinv[i] = rsqrtf((float)(v + 1));
        if (i == N - 1) g_rowstart[N] = base + incl;
    }
}

__global__ void k_scatter(const int* __restrict__ ei, int E) {
    int i = blockIdx.x * blockDim.x + threadIdx.x;
    int stride = gridDim.x * blockDim.x;
    int nv = E >> 2;
    const int4* s4p = (const int4*)ei;
    const int4* d4p = (const int4*)(ei + E);
    for (int v = i; v < nv; v += stride) {
        int4 s = s4p[v];
        int4 d = d4p[v];
        g_csr[atomicAdd(&g_cursor[d.x], 1)] = s.x;
        g_csr[atomicAdd(&g_cursor[d.y], 1)] = s.y;
        g_csr[atomicAdd(&g_cursor[d.z], 1)] = s.z;
        g_csr[atomicAdd(&g_cursor[d.w], 1)] = s.w;
    }
}

// ---------------- GEMM1: register-tiled. Block = 128 nodes, thread = 4 nodes x 4 cols ----------------
#define G1_NODES 128
#define G1_XPITCH 132
#define G1_SMEM ((128 * 32 + G1_NODES * G1_XPITCH) * 4)

__global__ void __launch_bounds__(256) k_gemm1(const float* __restrict__ x,
                                               const float* __restrict__ W1, int N) {
    extern __shared__ float sm[];
    float* Ws = sm;                    // [128][32]
    float* xs = sm + 128 * 32;         // [128][132] padded

    int t = threadIdx.x;
    int nodebase = blockIdx.x * G1_NODES;

    // load W1 (4096 floats = 1024 float4)
    {
        const float4* w4 = (const float4*)W1;
        float4* ws4 = (float4*)Ws;
        for (int i = t; i < 1024; i += 256) ws4[i] = w4[i];
    }
    // load x tile: 128 nodes x 32 float4 each
    for (int idx = t; idx < G1_NODES * 32; idx += 256) {
        int node = idx >> 5;
        int f4 = idx & 31;
        float4 v = make_float4(0.f, 0.f, 0.f, 0.f);
        int n = nodebase + node;
        if (n < N) v = *(const float4*)(x + (size_t)n * 128 + f4 * 4);
        *(float4*)(xs + node * G1_XPITCH + f4 * 4) = v;
    }
    __syncthreads();

    int c0 = (t & 7) * 4;
    int r0 = (t >> 3) * 4;
    float acc[4][4];
#pragma unroll
    for (int j = 0; j < 4; j++)
#pragma unroll
        for (int c = 0; c < 4; c++) acc[j][c] = 0.f;

#pragma unroll 4
    for (int k0 = 0; k0 < 128; k0 += 4) {
        float4 xr[4], w[4];
#pragma unroll
        for (int j = 0; j < 4; j++) xr[j] = *(float4*)(xs + (r0 + j) * G1_XPITCH + k0);
#pragma unroll
        for (int i = 0; i < 4; i++) w[i] = *(float4*)(Ws + (k0 + i) * 32 + c0);
#pragma unroll
        for (int j = 0; j < 4; j++) {
            acc[j][0] = fmaf(xr[j].x, w[0].x, acc[j][0]);
            acc[j][1] = fmaf(xr[j].x, w[0].y, acc[j][1]);
            acc[j][2] = fmaf(xr[j].x, w[0].z, acc[j][2]);
            acc[j][3] = fmaf(xr[j].x, w[0].w, acc[j][3]);
            acc[j][0] = fmaf(xr[j].y, w[1].x, acc[j][0]);
            acc[j][1] = fmaf(xr[j].y, w[1].y, acc[j][1]);
            acc[j][2] = fmaf(xr[j].y, w[1].z, acc[j][2]);
            acc[j][3] = fmaf(xr[j].y, w[1].w, acc[j][3]);
            acc[j][0] = fmaf(xr[j].z, w[2].x, acc[j][0]);
            acc[j][1] = fmaf(xr[j].z, w[2].y, acc[j][1]);
            acc[j][2] = fmaf(xr[j].z, w[2].z, acc[j][2]);
            acc[j][3] = fmaf(xr[j].z, w[2].w, acc[j][3]);
            acc[j][0] = fmaf(xr[j].w, w[3].x, acc[j][0]);
            acc[j][1] = fmaf(xr[j].w, w[3].y, acc[j][1]);
            acc[j][2] = fmaf(xr[j].w, w[3].z, acc[j][2]);
            acc[j][3] = fmaf(xr[j].w, w[3].w, acc[j][3]);
        }
    }

#pragma unroll
    for (int j = 0; j < 4; j++) {
        int n = nodebase + r0 + j;
        if (n < N) {
            float di = g_dinv[n];
            float4 o = make_float4(acc[j][0] * di, acc[j][1] * di, acc[j][2] * di, acc[j][3] * di);
            *(float4*)(g_h1s + (size_t)n * 32 + c0) = o;
        }
    }
}

// ---------------- agg layer 1 + relu + fused GEMM2 ----------------
__global__ void __launch_bounds__(256) k_agg1g2(const float* __restrict__ b1,
                                                const float* __restrict__ W2, int N) {
    __shared__ float W2s[32 * 32];
    for (int i = threadIdx.x; i < 32 * 32; i += blockDim.x) {
        int k = i >> 5, c = i & 31;
        W2s[i] = (c < NC) ? W2[k * NC + c] : 0.f;
    }
    __syncthreads();
    int lane = threadIdx.x & 31;
    int warp = (blockIdx.x * blockDim.x + threadIdx.x) >> 5;
    int nwarps = (gridDim.x * blockDim.x) >> 5;
    float bias = b1[lane];
    for (int n = warp; n < N; n += nwarps) {
        int r0 = g_rowstart[n], r1 = g_rowstart[n + 1];
        float acc = g_h1s[n * 32 + lane];  // self-loop
        int j = r0;
        for (; j + 4 <= r1; j += 4) {
            int s0 = __ldg(&g_csr[j]);
            int s1 = __ldg(&g_csr[j + 1]);
            int s2 = __ldg(&g_csr[j + 2]);
            int s3 = __ldg(&g_csr[j + 3]);
            float v0 = g_h1s[s0 * 32 + lane];
            float v1 = g_h1s[s1 * 32 + lane];
            float v2 = g_h1s[s2 * 32 + lane];
            float v3 = g_h1s[s3 * 32 + lane];
            acc += (v0 + v1) + (v2 + v3);
        }
        for (; j < r1; j++) acc += g_h1s[__ldg(&g_csr[j]) * 32 + lane];
        float di = g_dinv[n];
        float hv = fmaxf(di * acc + bias, 0.f);
        // fused GEMM2: zs = dinv * (h @ W2)
        float z = 0.f;
#pragma unroll
        for (int k = 0; k < 32; k++)
            z = fmaf(__shfl_sync(0xffffffffu, hv, k), W2s[k * 32 + lane], z);
        g_zs[n * 32 + lane] = (lane < NC) ? z * di : 0.f;
    }
}

// ---------------- agg layer 2 + bias + softmax + column log-sums + bf16 FX ----------------
__global__ void __launch_bounds__(256) k_agg2(const float* __restrict__ b2,
                                              float* __restrict__ out, int N) {
    __shared__ float scs[32];
    int lane = threadIdx.x & 31;
    if (threadIdx.x < 32) scs[threadIdx.x] = 0.f;
    __syncthreads();
    int warp = (blockIdx.x * blockDim.x + threadIdx.x) >> 5;
    int nwarps = (gridDim.x * blockDim.x) >> 5;
    float bias = (lane < NC) ? b2[lane] : 0.f;
    float nfacc = 0.f;
    for (int n = warp; n < N; n += nwarps) {
        int r0 = g_rowstart[n], r1 = g_rowstart[n + 1];
        float acc = g_zs[n * 32 + lane];  // self-loop
        int j = r0;
        for (; j + 4 <= r1; j += 4) {
            int s0 = __ldg(&g_csr[j]);
            int s1 = __ldg(&g_csr[j + 1]);
            int s2 = __ldg(&g_csr[j + 2]);
            int s3 = __ldg(&g_csr[j + 3]);
            float v0 = g_zs[s0 * 32 + lane];
            float v1 = g_zs[s1 * 32 + lane];
            float v2 = g_zs[s2 * 32 + lane];
            float v3 = g_zs[s3 * 32 + lane];
            acc += (v0 + v1) + (v2 + v3);
        }
        for (; j < r1; j++) acc += g_zs[__ldg(&g_csr[j]) * 32 + lane];
        float logit = (lane < NC) ? (g_dinv[n] * acc + bias) : -1e30f;
        float m = logit;
#pragma unroll
        for (int o = 16; o > 0; o >>= 1) m = fmaxf(m, __shfl_xor_sync(0xffffffffu, m, o));
        float p = (lane < NC) ? expf(logit - m) : 0.f;
        float s = p;
#pragma unroll
        for (int o = 16; o > 0; o >>= 1) s += __shfl_xor_sync(0xffffffffu, s, o);
        float fx = p / s;
        // bf16 packed copy for k_ff
        float fxhi = __shfl_down_sync(0xffffffffu, fx, 1);
        if ((lane & 1) == 0)
            g_fxh[n * 16 + (lane >> 1)] = __floats2bfloat162_rn(fx, fxhi);
        if (lane < NC) {
            out[(size_t)n * NC + lane] = fx;
            nfacc += logf(1.f - fx * fx);
        }
    }
    atomicAdd(&scs[lane], nfacc);
    __syncthreads();
    if (threadIdx.x < 32) {
        float v = scs[threadIdx.x];
        if (v != 0.f) atomicAdd(&g_colsum[threadIdx.x], (double)v);
    }
}

// ---------------- FF: half-warp per edge, bf162 gathers ----------------
__global__ void __launch_bounds__(256) k_ff(const int* __restrict__ ei,
                                            const float* __restrict__ ep, int E) {
    __shared__ float red[256];
    int lane = threadIdx.x & 31;
    int half = lane >> 4;        // 0 or 1
    int l16 = lane & 15;
    int warp = (blockIdx.x * blockDim.x + threadIdx.x) >> 5;
    int nwarps = (gridDim.x * blockDim.x) >> 5;
    float acc = 0.f;
    for (int base = warp * 2; base < E; base += nwarps * 2) {
        int e = base + half;
        bool valid = (e < E);
        int ec = valid ? e : 0;
        int s = ei[ec];
        int d = ei[E + ec];
        float pl = valid ? ep[ec] : 0.f;
        __nv_bfloat162 a = g_fxh[s * 16 + l16];
        __nv_bfloat162 b = g_fxh[d * 16 + l16];
        float2 fa = __bfloat1622float2(a);
        float2 fb = __bfloat1622float2(b);
        float v = fmaf(fa.x, fb.x, fa.y * fb.y);
#pragma unroll
        for (int o = 1; o <= 8; o <<= 1) v += __shfl_xor_sync(0xffffffffu, v, o);
        if (l16 == 0 && valid) {
            float df = v - pl;
            acc += df * df;
        }
    }
    red[threadIdx.x] = acc;
    __syncthreads();
    for (int off = 128; off > 0; off >>= 1) {
        if (threadIdx.x < off) red[threadIdx.x] += red[threadIdx.x + off];
        __syncthreads();
    }
    if (threadIdx.x == 0) atomicAdd(&g_mse, (double)red[0]);
}

// ---------------- final loss ----------------
__global__ void k_finish(float* __restrict__ out, int N, int E) {
    if (threadIdx.x == 0 && blockIdx.x == 0) {
        double preg = 0.0;
        for (int c = 0; c < NC; c++) {
            double S = g_colsum[c];
            preg -= log(1.0001 - exp(S));
        }
        double loss = g_mse / (double)E + 0.01 * preg;
        out[(size_t)N * NC] = (float)loss;
    }
}

// ---------------- launch ----------------
extern "C" void kernel_launch(void* const* d_in, const int* in_sizes, int n_in,
                              void* d_out, int out_size) {
    const float* x  = (const float*)d_in[0];
    const int*   ei = (const int*)d_in[1];
    const float* ep = (const float*)d_in[2];
    const float* W1 = (const float*)d_in[3];
    const float* b1 = (const float*)d_in[4];
    const float* W2 = (const float*)d_in[5];
    const float* b2 = (const float*)d_in[6];
    float* out = (float*)d_out;

    int N = in_sizes[0] / 128;   // 100000
    int E = in_sizes[2];         // 3200000
    int NB = (N + 1023) / 1024;  // 98

    static bool attr_done = false;
    if (!attr_done) {
        cudaFuncSetAttribute(k_gemm1, cudaFuncAttributeMaxDynamicSharedMemorySize, G1_SMEM);
        attr_done = true;
    }

    k_zero<<<256, 256>>>(N);
    k_hist<<<512, 256>>>(ei, E);
    k_scan1<<<NB, 1024>>>(N);
    k_scan3<<<NB, 1024>>>(N);
    k_scatter<<<512, 256>>>(ei, E);
    k_gemm1<<<(N + G1_NODES - 1) / G1_NODES, 256, G1_SMEM>>>(x, W1, N);
    k_agg1g2<<<784, 256>>>(b1, W2, N);
    k_agg2<<<784, 256>>>(b2, out, N);
    k_ff<<<1024, 256>>>(ei, ep, E);
    k_finish<<<1, 32>>>(out, N, E);
}

// round 7
// speedup vs baseline: 1.3930x; 1.2376x over previous
#include <cuda_runtime.h>
#include <cuda_bf16.h>
#include <math.h>

#define NMAX 100000
#define EMAX 3200000
#define NC   30

// ---------------- scratch ----------------
__device__ int    g_cnt[NMAX];
__device__ int    g_rowstart[NMAX + 1];
__device__ int    g_cursor[NMAX];
__device__ int    g_csr[EMAX];
__device__ float  g_dinv[NMAX];
__device__ float  g_h1s[NMAX * 32];      // dinv[n] * (x @ W1)[n,:]
__device__ float  g_zs[NMAX * 32];       // dinv[n] * (relu(...) @ W2)[n,:], padded
__device__ __nv_bfloat162 g_fxh[NMAX * 16];  // FX rows in bf16 (for k_ff only)
__device__ int    g_bsum[128];
__device__ double g_colsum[32];
__device__ double g_mse;

// ---------------- degree histogram (int4 edge loads) ----------------
__global__ void k_hist(const int* __restrict__ ei, int E) {
    int i = blockIdx.x * blockDim.x + threadIdx.x;
    int stride = gridDim.x * blockDim.x;
    int nv = E >> 2;
    const int4* d4p = (const int4*)(ei + E);
    for (int v = i; v < nv; v += stride) {
        int4 d = d4p[v];
        atomicAdd(&g_cnt[d.x], 1);
        atomicAdd(&g_cnt[d.y], 1);
        atomicAdd(&g_cnt[d.z], 1);
        atomicAdd(&g_cnt[d.w], 1);
    }
}

// block partial sums over 1024-chunks (+ zero the loss accumulators)
__global__ void k_scan1(int N) {
    __shared__ int sh[1024];
    int t = threadIdx.x;
    int i = blockIdx.x * 1024 + t;
    int v = (i < N) ? g_cnt[i] : 0;
    sh[t] = v;
    if (blockIdx.x == 0) {
        if (t < 32) g_colsum[t] = 0.0;
        if (t == 0) g_mse = 0.0;
    }
    __syncthreads();
    for (int off = 512; off > 0; off >>= 1) {
        if (t < off) sh[t] += sh[t + off];
        __syncthreads();
    }
    if (t == 0) g_bsum[blockIdx.x] = sh[0];
}

// per-block scan; block prefix over g_bsum computed inline by warp 0
__global__ void k_scan3(int N) {
    __shared__ int sh[1024];
    __shared__ int sbase;
    int t = threadIdx.x;
    int i = blockIdx.x * 1024 + t;
    int v = (i < N) ? g_cnt[i] : 0;
    sh[t] = v;
    if (t < 32) {
        int ssum = 0;
        for (int b = t; b < blockIdx.x; b += 32) ssum += g_bsum[b];
#pragma unroll
        for (int o = 16; o > 0; o >>= 1) ssum += __shfl_xor_sync(0xffffffffu, ssum, o);
        if (t == 0) sbase = ssum;
    }
    __syncthreads();
    for (int off = 1; off < 1024; off <<= 1) {
        int a = (t >= off) ? sh[t - off] : 0;
        __syncthreads();
        sh[t] += a;
        __syncthreads();
    }
    if (i < N) {
        int incl = sh[t];
        int base = sbase;
        int rs = base + incl - v;
        g_rowstart[i] = rs;
        g_cursor[i] = rs;
        g_dinv[i] = rsqrtf((float)(v + 1));
        if (i == N - 1) g_rowstart[N] = base + incl;
    }
}

__global__ void k_scatter(const int* __restrict__ ei, int E) {
    int i = blockIdx.x * blockDim.x + threadIdx.x;
    int stride = gridDim.x * blockDim.x;
    int nv = E >> 2;
    const int4* s4p = (const int4*)ei;
    const int4* d4p = (const int4*)(ei + E);
    for (int v = i; v < nv; v += stride) {
        int4 s = s4p[v];
        int4 d = d4p[v];
        g_csr[atomicAdd(&g_cursor[d.x], 1)] = s.x;
        g_csr[atomicAdd(&g_cursor[d.y], 1)] = s.y;
        g_csr[atomicAdd(&g_cursor[d.z], 1)] = s.z;
        g_csr[atomicAdd(&g_cursor[d.w], 1)] = s.w;
    }
}

// ---------------- GEMM1: register-tiled. Block = 128 nodes, thread = 4 nodes x 4 cols ----------------
#define G1_NODES 128
#define G1_XPITCH 132
#define G1_SMEM ((128 * 32 + G1_NODES * G1_XPITCH) * 4)

__global__ void __launch_bounds__(256) k_gemm1(const float* __restrict__ x,
                                               const float* __restrict__ W1, int N) {
    extern __shared__ float sm[];
    float* Ws = sm;                    // [128][32]
    float* xs = sm + 128 * 32;         // [128][132] padded

    int t = threadIdx.x;
    int nodebase = blockIdx.x * G1_NODES;

    {
        const float4* w4 = (const float4*)W1;
        float4* ws4 = (float4*)Ws;
        for (int i = t; i < 1024; i += 256) ws4[i] = w4[i];
    }
    for (int idx = t; idx < G1_NODES * 32; idx += 256) {
        int node = idx >> 5;
        int f4 = idx & 31;
        float4 v = make_float4(0.f, 0.f, 0.f, 0.f);
        int n = nodebase + node;
        if (n < N) v = *(const float4*)(x + (size_t)n * 128 + f4 * 4);
        *(float4*)(xs + node * G1_XPITCH + f4 * 4) = v;
    }
    __syncthreads();

    int c0 = (t & 7) * 4;
    int r0 = (t >> 3) * 4;
    float acc[4][4];
#pragma unroll
    for (int j = 0; j < 4; j++)
#pragma unroll
        for (int c = 0; c < 4; c++) acc[j][c] = 0.f;

#pragma unroll 4
    for (int k0 = 0; k0 < 128; k0 += 4) {
        float4 xr[4], w[4];
#pragma unroll
        for (int j = 0; j < 4; j++) xr[j] = *(float4*)(xs + (r0 + j) * G1_XPITCH + k0);
#pragma unroll
        for (int i = 0; i < 4; i++) w[i] = *(float4*)(Ws + (k0 + i) * 32 + c0);
#pragma unroll
        for (int j = 0; j < 4; j++) {
            acc[j][0] = fmaf(xr[j].x, w[0].x, acc[j][0]);
            acc[j][1] = fmaf(xr[j].x, w[0].y, acc[j][1]);
            acc[j][2] = fmaf(xr[j].x, w[0].z, acc[j][2]);
            acc[j][3] = fmaf(xr[j].x, w[0].w, acc[j][3]);
            acc[j][0] = fmaf(xr[j].y, w[1].x, acc[j][0]);
            acc[j][1] = fmaf(xr[j].y, w[1].y, acc[j][1]);
            acc[j][2] = fmaf(xr[j].y, w[1].z, acc[j][2]);
            acc[j][3] = fmaf(xr[j].y, w[1].w, acc[j][3]);
            acc[j][0] = fmaf(xr[j].z, w[2].x, acc[j][0]);
            acc[j][1] = fmaf(xr[j].z, w[2].y, acc[j][1]);
            acc[j][2] = fmaf(xr[j].z, w[2].z, acc[j][2]);
            acc[j][3] = fmaf(xr[j].z, w[2].w, acc[j][3]);
            acc[j][0] = fmaf(xr[j].w, w[3].x, acc[j][0]);
            acc[j][1] = fmaf(xr[j].w, w[3].y, acc[j][1]);
            acc[j][2] = fmaf(xr[j].w, w[3].z, acc[j][2]);
            acc[j][3] = fmaf(xr[j].w, w[3].w, acc[j][3]);
        }
    }

#pragma unroll
    for (int j = 0; j < 4; j++) {
        int n = nodebase + r0 + j;
        if (n < N) {
            float di = g_dinv[n];
            float4 o = make_float4(acc[j][0] * di, acc[j][1] * di, acc[j][2] * di, acc[j][3] * di);
            *(float4*)(g_h1s + (size_t)n * 32 + c0) = o;
        }
    }
}

// ---------------- shared gather helper: sum rows tbl[s*32+lane] over a CSR range ----------------
__device__ __forceinline__ float csr_row_sum(const float* __restrict__ tbl,
                                             int r0, int r1, int lane, float acc) {
    for (int base = r0; base < r1; base += 32) {
        int rem = r1 - base;
        int cnt = rem < 32 ? rem : 32;
        int idx = (lane < cnt) ? __ldg(&g_csr[base + lane]) : 0;
        int i = 0;
        for (; i + 8 <= cnt; i += 8) {
            int s0 = __shfl_sync(0xffffffffu, idx, i);
            int s1 = __shfl_sync(0xffffffffu, idx, i + 1);
            int s2 = __shfl_sync(0xffffffffu, idx, i + 2);
            int s3 = __shfl_sync(0xffffffffu, idx, i + 3);
            int s4 = __shfl_sync(0xffffffffu, idx, i + 4);
            int s5 = __shfl_sync(0xffffffffu, idx, i + 5);
            int s6 = __shfl_sync(0xffffffffu, idx, i + 6);
            int s7 = __shfl_sync(0xffffffffu, idx, i + 7);
            float v0 = __ldg(&tbl[s0 * 32 + lane]);
            float v1 = __ldg(&tbl[s1 * 32 + lane]);
            float v2 = __ldg(&tbl[s2 * 32 + lane]);
            float v3 = __ldg(&tbl[s3 * 32 + lane]);
            float v4 = __ldg(&tbl[s4 * 32 + lane]);
            float v5 = __ldg(&tbl[s5 * 32 + lane]);
            float v6 = __ldg(&tbl[s6 * 32 + lane]);
            float v7 = __ldg(&tbl[s7 * 32 + lane]);
            acc += ((v0 + v1) + (v2 + v3)) + ((v4 + v5) + (v6 + v7));
        }
        for (; i < cnt; i++) {
            int s = __shfl_sync(0xffffffffu, idx, i);
            acc += __ldg(&tbl[s * 32 + lane]);
        }
    }
    return acc;
}

// ---------------- agg layer 1 + relu + fused GEMM2 ----------------
__global__ void __launch_bounds__(256) k_agg1g2(const float* __restrict__ b1,
                                                const float* __restrict__ W2, int N) {
    __shared__ float W2s[32 * 32];
    for (int i = threadIdx.x; i < 32 * 32; i += blockDim.x) {
        int k = i >> 5, c = i & 31;
        W2s[i] = (c < NC) ? W2[k * NC + c] : 0.f;
    }
    __syncthreads();
    int lane = threadIdx.x & 31;
    int warp = (blockIdx.x * blockDim.x + threadIdx.x) >> 5;
    int nwarps = (gridDim.x * blockDim.x) >> 5;
    float bias = b1[lane];
    int chunk = (N + nwarps - 1) / nwarps;
    int n0 = warp * chunk;
    int n1 = min(N, n0 + chunk);
    for (int n = n0; n < n1; n++) {
        int r0 = g_rowstart[n], r1 = g_rowstart[n + 1];
        float acc = csr_row_sum(g_h1s, r0, r1, lane, g_h1s[n * 32 + lane]);
        float di = g_dinv[n];
        float hv = fmaxf(di * acc + bias, 0.f);
        float z = 0.f;
#pragma unroll
        for (int k = 0; k < 32; k++)
            z = fmaf(__shfl_sync(0xffffffffu, hv, k), W2s[k * 32 + lane], z);
        g_zs[n * 32 + lane] = (lane < NC) ? z * di : 0.f;
    }
}

// ---------------- agg layer 2 + bias + softmax + column log-sums + bf16 FX ----------------
__global__ void __launch_bounds__(256) k_agg2(const float* __restrict__ b2,
                                              float* __restrict__ out, int N) {
    __shared__ float scs[32];
    int lane = threadIdx.x & 31;
    if (threadIdx.x < 32) scs[threadIdx.x] = 0.f;
    __syncthreads();
    int warp = (blockIdx.x * blockDim.x + threadIdx.x) >> 5;
    int nwarps = (gridDim.x * blockDim.x) >> 5;
    float bias = (lane < NC) ? b2[lane] : 0.f;
    float nfacc = 0.f;
    int chunk = (N + nwarps - 1) / nwarps;
    int n0 = warp * chunk;
    int n1 = min(N, n0 + chunk);
    for (int n = n0; n < n1; n++) {
        int r0 = g_rowstart[n], r1 = g_rowstart[n + 1];
        float acc = csr_row_sum(g_zs, r0, r1, lane, g_zs[n * 32 + lane]);
        float logit = (lane < NC) ? (g_dinv[n] * acc + bias) : -1e30f;
        float m = logit;
#pragma unroll
        for (int o = 16; o > 0; o >>= 1) m = fmaxf(m, __shfl_xor_sync(0xffffffffu, m, o));
        float p = (lane < NC) ? expf(logit - m) : 0.f;
        float s = p;
#pragma unroll
        for (int o = 16; o > 0; o >>= 1) s += __shfl_xor_sync(0xffffffffu, s, o);
        float fx = p / s;
        float fxhi = __shfl_down_sync(0xffffffffu, fx, 1);
        if ((lane & 1) == 0)
            g_fxh[n * 16 + (lane >> 1)] = __floats2bfloat162_rn(fx, fxhi);
        if (lane < NC) {
            out[(size_t)n * NC + lane] = fx;
            nfacc += logf(1.f - fx * fx);
        }
    }
    atomicAdd(&scs[lane], nfacc);
    __syncthreads();
    if (threadIdx.x < 32) {
        float v = scs[threadIdx.x];
        if (v != 0.f) atomicAdd(&g_colsum[threadIdx.x], (double)v);
    }
}

// ---------------- FF: 8 lanes per edge (4 edges/warp), unroll x2 ----------------
__global__ void __launch_bounds__(256) k_ff(const int* __restrict__ ei,
                                            const float* __restrict__ ep, int E) {
    __shared__ float red[256];
    int lane = threadIdx.x & 31;
    int grp = lane >> 3;     // 0..3
    int l8 = lane & 7;       // 0..7
    int warp = (blockIdx.x * blockDim.x + threadIdx.x) >> 5;
    int nwarps = (gridDim.x * blockDim.x) >> 5;
    float acc = 0.f;
    for (int base = warp * 8; base < E; base += nwarps * 8) {
#pragma unroll
        for (int u = 0; u < 2; u++) {
            int e = base + u * 4 + grp;
            bool valid = (e < E);
            int ec = valid ? e : 0;
            int s = __ldg(&ei[ec]);
            int d = __ldg(&ei[E + ec]);
            float pl = valid ? __ldg(&ep[ec]) : 0.f;
            uint2 ar = *(const uint2*)(g_fxh + s * 16 + l8 * 2);
            uint2 br = *(const uint2*)(g_fxh + d * 16 + l8 * 2);
            float2 a0 = __bfloat1622float2(*(__nv_bfloat162*)&ar.x);
            float2 a1 = __bfloat1622float2(*(__nv_bfloat162*)&ar.y);
            float2 b0 = __bfloat1622float2(*(__nv_bfloat162*)&br.x);
            float2 b1 = __bfloat1622float2(*(__nv_bfloat162*)&br.y);
            float v = a0.x * b0.x;
            v = fmaf(a0.y, b0.y, v);
            v = fmaf(a1.x, b1.x, v);
            v = fmaf(a1.y, b1.y, v);
#pragma unroll
            for (int o = 1; o <= 4; o <<= 1) v += __shfl_xor_sync(0xffffffffu, v, o);
            if (l8 == 0 && valid) {
                float df = v - pl;
                acc += df * df;
            }
        }
    }
    red[threadIdx.x] = acc;
    __syncthreads();
    for (int off = 128; off > 0; off >>= 1) {
        if (threadIdx.x < off) red[threadIdx.x] += red[threadIdx.x + off];
        __syncthreads();
    }
    if (threadIdx.x == 0) atomicAdd(&g_mse, (double)red[0]);
}

// ---------------- final loss ----------------
__global__ void k_finish(float* __restrict__ out, int N, int E) {
    if (threadIdx.x == 0 && blockIdx.x == 0) {
        double preg = 0.0;
        for (int c = 0; c < NC; c++) {
            double S = g_colsum[c];
            preg -= log(1.0001 - exp(S));
        }
        double loss = g_mse / (double)E + 0.01 * preg;
        out[(size_t)N * NC] = (float)loss;
    }
}

// ---------------- launch ----------------
extern "C" void kernel_launch(void* const* d_in, const int* in_sizes, int n_in,
                              void* d_out, int out_size) {
    const float* x  = (const float*)d_in[0];
    const int*   ei = (const int*)d_in[1];
    const float* ep = (const float*)d_in[2];
    const float* W1 = (const float*)d_in[3];
    const float* b1 = (const float*)d_in[4];
    const float* W2 = (const float*)d_in[5];
    const float* b2 = (const float*)d_in[6];
    float* out = (float*)d_out;

    int N = in_sizes[0] / 128;   // 100000
    int E = in_sizes[2];         // 3200000
    int NB = (N + 1023) / 1024;  // 98

    // Idempotent, stream-free setup: same behavior on every call (no static guards).
    cudaFuncSetAttribute(k_gemm1, cudaFuncAttributeMaxDynamicSharedMemorySize, G1_SMEM);
    void* cnt_ptr = nullptr;
    cudaGetSymbolAddress(&cnt_ptr, g_cnt);

    cudaMemsetAsync(cnt_ptr, 0, (size_t)N * sizeof(int), 0);
    k_hist<<<1024, 256>>>(ei, E);                                   // launch 0
    k_scan1<<<NB, 1024>>>(N);                                       // launch 1
    k_scan3<<<NB, 1024>>>(N);                                       // launch 2
    k_gemm1<<<(N + G1_NODES - 1) / G1_NODES, 256, G1_SMEM>>>(x, W1, N);  // launch 3 (profiled)
    k_scatter<<<1024, 256>>>(ei, E);                                // launch 4
    k_agg1g2<<<1184, 256>>>(b1, W2, N);                             // launch 5
    k_agg2<<<1184, 256>>>(b2, out, N);                              // launch 6
    k_ff<<<1184, 256>>>(ei, ep, E);                                 // launch 7
    k_finish<<<1, 32>>>(out, N, E);                                 // launch 8
}

// round 8
// speedup vs baseline: 1.4072x; 1.0102x over previous
#include <cuda_runtime.h>
#include <cuda_bf16.h>
#include <math.h>

#define NMAX 100000
#define EMAX 3200000
#define NC   30

// ---------------- scratch ----------------
__device__ int    g_cnt[NMAX];
__device__ int    g_rowstart[NMAX + 1];
__device__ int    g_cursor[NMAX];
__device__ int    g_csr[EMAX];
__device__ float  g_dinv[NMAX];
__device__ float  g_h1s[NMAX * 32];      // dinv[n] * (x @ W1)[n,:]
__device__ float  g_zs[NMAX * 32];       // dinv[n] * (relu(...) @ W2)[n,:], padded
__device__ __nv_bfloat162 g_fxh[NMAX * 16];  // FX rows in bf16 (for k_ff only)
__device__ int    g_bsum[128];
__device__ double g_colsum[32];
__device__ double g_mse;

// ---------------- degree histogram (int4 edge loads) ----------------
__global__ void k_hist(const int* __restrict__ ei, int E) {
    int i = blockIdx.x * blockDim.x + threadIdx.x;
    int stride = gridDim.x * blockDim.x;
    int nv = E >> 2;
    const int4* d4p = (const int4*)(ei + E);
    for (int v = i; v < nv; v += stride) {
        int4 d = d4p[v];
        atomicAdd(&g_cnt[d.x], 1);
        atomicAdd(&g_cnt[d.y], 1);
        atomicAdd(&g_cnt[d.z], 1);
        atomicAdd(&g_cnt[d.w], 1);
    }
}

// block partial sums over 1024-chunks (+ zero the loss accumulators)
__global__ void k_scan1(int N) {
    __shared__ int sh[1024];
    int t = threadIdx.x;
    int i = blockIdx.x * 1024 + t;
    int v = (i < N) ? g_cnt[i] : 0;
    sh[t] = v;
    if (blockIdx.x == 0) {
        if (t < 32) g_colsum[t] = 0.0;
        if (t == 0) g_mse = 0.0;
    }
    __syncthreads();
    for (int off = 512; off > 0; off >>= 1) {
        if (t < off) sh[t] += sh[t + off];
        __syncthreads();
    }
    if (t == 0) g_bsum[blockIdx.x] = sh[0];
}

// per-block scan; block prefix over g_bsum computed inline by warp 0
__global__ void k_scan3(int N) {
    __shared__ int sh[1024];
    __shared__ int sbase;
    int t = threadIdx.x;
    int i = blockIdx.x * 1024 + t;
    int v = (i < N) ? g_cnt[i] : 0;
    sh[t] = v;
    if (t < 32) {
        int ssum = 0;
        for (int b = t; b < blockIdx.x; b += 32) ssum += g_bsum[b];
#pragma unroll
        for (int o = 16; o > 0; o >>= 1) ssum += __shfl_xor_sync(0xffffffffu, ssum, o);
        if (t == 0) sbase = ssum;
    }
    __syncthreads();
    for (int off = 1; off < 1024; off <<= 1) {
        int a = (t >= off) ? sh[t - off] : 0;
        __syncthreads();
        sh[t] += a;
        __syncthreads();
    }
    if (i < N) {
        int incl = sh[t];
        int base = sbase;
        int rs = base + incl - v;
        g_rowstart[i] = rs;
        g_cursor[i] = rs;
        g_dinv[i] = rsqrtf((float)(v + 1));
        if (i == N - 1) g_rowstart[N] = base + incl;
    }
}

__global__ void k_scatter(const int* __restrict__ ei, int E) {
    int i = blockIdx.x * blockDim.x + threadIdx.x;
    int stride = gridDim.x * blockDim.x;
    int nv = E >> 2;
    const int4* s4p = (const int4*)ei;
    const int4* d4p = (const int4*)(ei + E);
    for (int v = i; v < nv; v += stride) {
        int4 s = s4p[v];
        int4 d = d4p[v];
        g_csr[atomicAdd(&g_cursor[d.x], 1)] = s.x;
        g_csr[atomicAdd(&g_cursor[d.y], 1)] = s.y;
        g_csr[atomicAdd(&g_cursor[d.z], 1)] = s.z;
        g_csr[atomicAdd(&g_cursor[d.w], 1)] = s.w;
    }
}

// ---------------- GEMM1: register-tiled. Block = 64 nodes, thread = 2 nodes x 4 cols ----------------
// smem ~49 KB/block -> 4 blocks/SM (32 warps) instead of 2 (16 warps): latency-bound fix.
#define G1_NODES 64
#define G1_XPITCH 132
#define G1_SMEM ((128 * 32 + G1_NODES * G1_XPITCH) * 4)

__global__ void __launch_bounds__(256) k_gemm1(const float* __restrict__ x,
                                               const float* __restrict__ W1, int N) {
    extern __shared__ float sm[];
    float* Ws = sm;                    // [128][32]
    float* xs = sm + 128 * 32;         // [64][132] padded

    int t = threadIdx.x;
    int nodebase = blockIdx.x * G1_NODES;

    {
        const float4* w4 = (const float4*)W1;
        float4* ws4 = (float4*)Ws;
        for (int i = t; i < 1024; i += 256) ws4[i] = w4[i];
    }
    for (int idx = t; idx < G1_NODES * 32; idx += 256) {
        int node = idx >> 5;
        int f4 = idx & 31;
        float4 v = make_float4(0.f, 0.f, 0.f, 0.f);
        int n = nodebase + node;
        if (n < N) v = *(const float4*)(x + (size_t)n * 128 + f4 * 4);
        *(float4*)(xs + node * G1_XPITCH + f4 * 4) = v;
    }
    __syncthreads();

    int c0 = (t & 7) * 4;
    int r0 = (t >> 3) * 2;
    float acc[2][4];
#pragma unroll
    for (int j = 0; j < 2; j++)
#pragma unroll
        for (int c = 0; c < 4; c++) acc[j][c] = 0.f;

#pragma unroll 4
    for (int k0 = 0; k0 < 128; k0 += 4) {
        float4 xr[2], w[4];
#pragma unroll
        for (int j = 0; j < 2; j++) xr[j] = *(float4*)(xs + (r0 + j) * G1_XPITCH + k0);
#pragma unroll
        for (int i = 0; i < 4; i++) w[i] = *(float4*)(Ws + (k0 + i) * 32 + c0);
#pragma unroll
        for (int j = 0; j < 2; j++) {
            acc[j][0] = fmaf(xr[j].x, w[0].x, acc[j][0]);
            acc[j][1] = fmaf(xr[j].x, w[0].y, acc[j][1]);
            acc[j][2] = fmaf(xr[j].x, w[0].z, acc[j][2]);
            acc[j][3] = fmaf(xr[j].x, w[0].w, acc[j][3]);
            acc[j][0] = fmaf(xr[j].y, w[1].x, acc[j][0]);
            acc[j][1] = fmaf(xr[j].y, w[1].y, acc[j][1]);
            acc[j][2] = fmaf(xr[j].y, w[1].z, acc[j][2]);
            acc[j][3] = fmaf(xr[j].y, w[1].w, acc[j][3]);
            acc[j][0] = fmaf(xr[j].z, w[2].x, acc[j][0]);
            acc[j][1] = fmaf(xr[j].z, w[2].y, acc[j][1]);
            acc[j][2] = fmaf(xr[j].z, w[2].z, acc[j][2]);
            acc[j][3] = fmaf(xr[j].z, w[2].w, acc[j][3]);
            acc[j][0] = fmaf(xr[j].w, w[3].x, acc[j][0]);
            acc[j][1] = fmaf(xr[j].w, w[3].y, acc[j][1]);
            acc[j][2] = fmaf(xr[j].w, w[3].z, acc[j][2]);
            acc[j][3] = fmaf(xr[j].w, w[3].w, acc[j][3]);
        }
    }

#pragma unroll
    for (int j = 0; j < 2; j++) {
        int n = nodebase + r0 + j;
        if (n < N) {
            float di = g_dinv[n];
            float4 o = make_float4(acc[j][0] * di, acc[j][1] * di, acc[j][2] * di, acc[j][3] * di);
            *(float4*)(g_h1s + (size_t)n * 32 + c0) = o;
        }
    }
}

// ---------------- shared gather helper: sum rows tbl[s*32+lane] over a CSR range ----------------
__device__ __forceinline__ float csr_row_sum(const float* __restrict__ tbl,
                                             int r0, int r1, int lane, float acc) {
    for (int base = r0; base < r1; base += 32) {
        int rem = r1 - base;
        int cnt = rem < 32 ? rem : 32;
        int idx = (lane < cnt) ? __ldg(&g_csr[base + lane]) : 0;
        int i = 0;
        for (; i + 8 <= cnt; i += 8) {
            int s0 = __shfl_sync(0xffffffffu, idx, i);
            int s1 = __shfl_sync(0xffffffffu, idx, i + 1);
            int s2 = __shfl_sync(0xffffffffu, idx, i + 2);
            int s3 = __shfl_sync(0xffffffffu, idx, i + 3);
            int s4 = __shfl_sync(0xffffffffu, idx, i + 4);
            int s5 = __shfl_sync(0xffffffffu, idx, i + 5);
            int s6 = __shfl_sync(0xffffffffu, idx, i + 6);
            int s7 = __shfl_sync(0xffffffffu, idx, i + 7);
            float v0 = __ldg(&tbl[s0 * 32 + lane]);
            float v1 = __ldg(&tbl[s1 * 32 + lane]);
            float v2 = __ldg(&tbl[s2 * 32 + lane]);
            float v3 = __ldg(&tbl[s3 * 32 + lane]);
            float v4 = __ldg(&tbl[s4 * 32 + lane]);
            float v5 = __ldg(&tbl[s5 * 32 + lane]);
            float v6 = __ldg(&tbl[s6 * 32 + lane]);
            float v7 = __ldg(&tbl[s7 * 32 + lane]);
            acc += ((v0 + v1) + (v2 + v3)) + ((v4 + v5) + (v6 + v7));
        }
        for (; i < cnt; i++) {
            int s = __shfl_sync(0xffffffffu, idx, i);
            acc += __ldg(&tbl[s * 32 + lane]);
        }
    }
    return acc;
}

// ---------------- agg layer 1 + relu + fused GEMM2 ----------------
__global__ void __launch_bounds__(256) k_agg1g2(const float* __restrict__ b1,
                                                const float* __restrict__ W2, int N) {
    __shared__ float W2s[32 * 32];
    for (int i = threadIdx.x; i < 32 * 32; i += blockDim.x) {
        int k = i >> 5, c = i & 31;
        W2s[i] = (c < NC) ? W2[k * NC + c] : 0.f;
    }
    __syncthreads();
    int lane = threadIdx.x & 31;
    int warp = (blockIdx.x * blockDim.x + threadIdx.x) >> 5;
    int nwarps = (gridDim.x * blockDim.x) >> 5;
    float bias = b1[lane];
    int chunk = (N + nwarps - 1) / nwarps;
    int n0 = warp * chunk;
    int n1 = min(N, n0 + chunk);
    for (int n = n0; n < n1; n++) {
        int r0 = g_rowstart[n], r1 = g_rowstart[n + 1];
        float acc = csr_row_sum(g_h1s, r0, r1, lane, g_h1s[n * 32 + lane]);
        float di = g_dinv[n];
        float hv = fmaxf(di * acc + bias, 0.f);
        float z = 0.f;
#pragma unroll
        for (int k = 0; k < 32; k++)
            z = fmaf(__shfl_sync(0xffffffffu, hv, k), W2s[k * 32 + lane], z);
        g_zs[n * 32 + lane] = (lane < NC) ? z * di : 0.f;
    }
}

// ---------------- agg layer 2 + bias + softmax + column log-sums + bf16 FX ----------------
__global__ void __launch_bounds__(256) k_agg2(const float* __restrict__ b2,
                                              float* __restrict__ out, int N) {
    __shared__ float scs[32];
    int lane = threadIdx.x & 31;
    if (threadIdx.x < 32) scs[threadIdx.x] = 0.f;
    __syncthreads();
    int warp = (blockIdx.x * blockDim.x + threadIdx.x) >> 5;
    int nwarps = (gridDim.x * blockDim.x) >> 5;
    float bias = (lane < NC) ? b2[lane] : 0.f;
    float nfacc = 0.f;
    int chunk = (N + nwarps - 1) / nwarps;
    int n0 = warp * chunk;
    int n1 = min(N, n0 + chunk);
    for (int n = n0; n < n1; n++) {
        int r0 = g_rowstart[n], r1 = g_rowstart[n + 1];
        float acc = csr_row_sum(g_zs, r0, r1, lane, g_zs[n * 32 + lane]);
        float logit = (lane < NC) ? (g_dinv[n] * acc + bias) : -1e30f;
        float m = logit;
#pragma unroll
        for (int o = 16; o > 0; o >>= 1) m = fmaxf(m, __shfl_xor_sync(0xffffffffu, m, o));
        float p = (lane < NC) ? expf(logit - m) : 0.f;
        float s = p;
#pragma unroll
        for (int o = 16; o > 0; o >>= 1) s += __shfl_xor_sync(0xffffffffu, s, o);
        float fx = p / s;
        float fxhi = __shfl_down_sync(0xffffffffu, fx, 1);
        if ((lane & 1) == 0)
            g_fxh[n * 16 + (lane >> 1)] = __floats2bfloat162_rn(fx, fxhi);
        if (lane < NC) {
            out[(size_t)n * NC + lane] = fx;
            nfacc += logf(1.f - fx * fx);
        }
    }
    atomicAdd(&scs[lane], nfacc);
    __syncthreads();
    if (threadIdx.x < 32) {
        float v = scs[threadIdx.x];
        if (v != 0.f) atomicAdd(&g_colsum[threadIdx.x], (double)v);
    }
}

// ---------------- FF: 8 lanes per edge (4 edges/warp), unroll x2 ----------------
__global__ void __launch_bounds__(256) k_ff(const int* __restrict__ ei,
                                            const float* __restrict__ ep, int E) {
    __shared__ float red[256];
    int lane = threadIdx.x & 31;
    int grp = lane >> 3;     // 0..3
    int l8 = lane & 7;       // 0..7
    int warp = (blockIdx.x * blockDim.x + threadIdx.x) >> 5;
    int nwarps = (gridDim.x * blockDim.x) >> 5;
    float acc = 0.f;
    for (int base = warp * 8; base < E; base += nwarps * 8) {
#pragma unroll
        for (int u = 0; u < 2; u++) {
            int e = base + u * 4 + grp;
            bool valid = (e < E);
            int ec = valid ? e : 0;
            int s = __ldg(&ei[ec]);
            int d = __ldg(&ei[E + ec]);
            float pl = valid ? __ldg(&ep[ec]) : 0.f;
            uint2 ar = *(const uint2*)(g_fxh + s * 16 + l8 * 2);
            uint2 br = *(const uint2*)(g_fxh + d * 16 + l8 * 2);
            float2 a0 = __bfloat1622float2(*(__nv_bfloat162*)&ar.x);
            float2 a1 = __bfloat1622float2(*(__nv_bfloat162*)&ar.y);
            float2 b0 = __bfloat1622float2(*(__nv_bfloat162*)&br.x);
            float2 b1 = __bfloat1622float2(*(__nv_bfloat162*)&br.y);
            float v = a0.x * b0.x;
            v = fmaf(a0.y, b0.y, v);
            v = fmaf(a1.x, b1.x, v);
            v = fmaf(a1.y, b1.y, v);
#pragma unroll
            for (int o = 1; o <= 4; o <<= 1) v += __shfl_xor_sync(0xffffffffu, v, o);
            if (l8 == 0 && valid) {
                float df = v - pl;
                acc += df * df;
            }
        }
    }
    red[threadIdx.x] = acc;
    __syncthreads();
    for (int off = 128; off > 0; off >>= 1) {
        if (threadIdx.x < off) red[threadIdx.x] += red[threadIdx.x + off];
        __syncthreads();
    }
    if (threadIdx.x == 0) atomicAdd(&g_mse, (double)red[0]);
}

// ---------------- final loss ----------------
__global__ void k_finish(float* __restrict__ out, int N, int E) {
    if (threadIdx.x == 0 && blockIdx.x == 0) {
        double preg = 0.0;
        for (int c = 0; c < NC; c++) {
            double S = g_colsum[c];
            preg -= log(1.0001 - exp(S));
        }
        double loss = g_mse / (double)E + 0.01 * preg;
        out[(size_t)N * NC] = (float)loss;
    }
}

// ---------------- launch ----------------
extern "C" void kernel_launch(void* const* d_in, const int* in_sizes, int n_in,
                              void* d_out, int out_size) {
    const float* x  = (const float*)d_in[0];
    const int*   ei = (const int*)d_in[1];
    const float* ep = (const float*)d_in[2];
    const float* W1 = (const float*)d_in[3];
    const float* b1 = (const float*)d_in[4];
    const float* W2 = (const float*)d_in[5];
    const float* b2 = (const float*)d_in[6];
    float* out = (float*)d_out;

    int N = in_sizes[0] / 128;   // 100000
    int E = in_sizes[2];         // 3200000
    int NB = (N + 1023) / 1024;  // 98

    // Idempotent, stream-free setup: same behavior on every call (no static guards).
    cudaFuncSetAttribute(k_gemm1, cudaFuncAttributeMaxDynamicSharedMemorySize, G1_SMEM);
    void* cnt_ptr = nullptr;
    cudaGetSymbolAddress(&cnt_ptr, g_cnt);

    cudaMemsetAsync(cnt_ptr, 0, (size_t)N * sizeof(int), 0);
    k_hist<<<1024, 256>>>(ei, E);                                   // launch 0
    k_scan1<<<NB, 1024>>>(N);                                       // launch 1
    k_scan3<<<NB, 1024>>>(N);                                       // launch 2
    k_gemm1<<<(N + G1_NODES - 1) / G1_NODES, 256, G1_SMEM>>>(x, W1, N);  // launch 3 (profiled)
    k_scatter<<<1024, 256>>>(ei, E);                                // launch 4
    k_agg1g2<<<1184, 256>>>(b1, W2, N);                             // launch 5
    k_agg2<<<1184, 256>>>(b2, out, N);                              // launch 6
    k_ff<<<1184, 256>>>(ei, ep, E);                                 // launch 7
    k_finish<<<1, 32>>>(out, N, E);                                 // launch 8
}

// round 9
// speedup vs baseline: 1.4174x; 1.0072x over previous
#include <cuda_runtime.h>
#include <cuda_bf16.h>
#include <math.h>

#define NMAX 100000
#define EMAX 3200000
#define NC   30

// ---------------- scratch ----------------
__device__ int    g_cnt[NMAX];
__device__ int    g_rowstart[NMAX + 1];
__device__ int    g_cursor[NMAX];
__device__ int    g_csr[EMAX];
__device__ float  g_dinv[NMAX];
__device__ float  g_h1s[NMAX * 32];      // dinv[n] * (x @ W1)[n,:]
__device__ float  g_zs[NMAX * 32];       // dinv[n] * (relu(...) @ W2)[n,:], padded
__device__ __nv_bfloat162 g_fxh[NMAX * 16];  // FX rows in bf16 (for k_ff only)
__device__ int    g_bsum[128];
__device__ double g_colsum[32];
__device__ double g_mse;

// ---------------- degree histogram (int4 edge loads) ----------------
__global__ void k_hist(const int* __restrict__ ei, int E) {
    int i = blockIdx.x * blockDim.x + threadIdx.x;
    int stride = gridDim.x * blockDim.x;
    int nv = E >> 2;
    const int4* d4p = (const int4*)(ei + E);
    for (int v = i; v < nv; v += stride) {
        int4 d = d4p[v];
        atomicAdd(&g_cnt[d.x], 1);
        atomicAdd(&g_cnt[d.y], 1);
        atomicAdd(&g_cnt[d.z], 1);
        atomicAdd(&g_cnt[d.w], 1);
    }
}

// block partial sums over 1024-chunks (+ dinv + zero the loss accumulators)
__global__ void k_scan1(int N) {
    __shared__ int sh[1024];
    int t = threadIdx.x;
    int i = blockIdx.x * 1024 + t;
    int v = (i < N) ? g_cnt[i] : 0;
    sh[t] = v;
    if (i < N) g_dinv[i] = rsqrtf((float)(v + 1));   // deg = in-degree + self-loop
    if (blockIdx.x == 0) {
        if (t < 32) g_colsum[t] = 0.0;
        if (t == 0) g_mse = 0.0;
    }
    __syncthreads();
    for (int off = 512; off > 0; off >>= 1) {
        if (t < off) sh[t] += sh[t + off];
        __syncthreads();
    }
    if (t == 0) g_bsum[blockIdx.x] = sh[0];
}

// per-block scan; block prefix over g_bsum computed inline by warp 0
__global__ void k_scan3(int N) {
    __shared__ int sh[1024];
    __shared__ int sbase;
    int t = threadIdx.x;
    int i = blockIdx.x * 1024 + t;
    int v = (i < N) ? g_cnt[i] : 0;
    sh[t] = v;
    if (t < 32) {
        int ssum = 0;
        for (int b = t; b < blockIdx.x; b += 32) ssum += g_bsum[b];
#pragma unroll
        for (int o = 16; o > 0; o >>= 1) ssum += __shfl_xor_sync(0xffffffffu, ssum, o);
        if (t == 0) sbase = ssum;
    }
    __syncthreads();
    for (int off = 1; off < 1024; off <<= 1) {
        int a = (t >= off) ? sh[t - off] : 0;
        __syncthreads();
        sh[t] += a;
        __syncthreads();
    }
    if (i < N) {
        int incl = sh[t];
        int base = sbase;
        int rs = base + incl - v;
        g_rowstart[i] = rs;
        g_cursor[i] = rs;
        if (i == N - 1) g_rowstart[N] = base + incl;
    }
}

// ---------------- fused scatter + GEMM1 (independent work, one launch) ----------------
#define G1_NODES 64
#define G1_XPITCH 132
#define G1_SMEM ((128 * 32 + G1_NODES * G1_XPITCH) * 4)
#define SBLK 1184   // scatter blocks

__device__ __forceinline__ void scatter_body(const int* __restrict__ ei, int E, int vbid) {
    int i = vbid * 256 + threadIdx.x;
    int stride = SBLK * 256;
    int nv = E >> 2;
    const int4* s4p = (const int4*)ei;
    const int4* d4p = (const int4*)(ei + E);
    for (int v = i; v < nv; v += stride) {
        int4 s = s4p[v];
        int4 d = d4p[v];
        g_csr[atomicAdd(&g_cursor[d.x], 1)] = s.x;
        g_csr[atomicAdd(&g_cursor[d.y], 1)] = s.y;
        g_csr[atomicAdd(&g_cursor[d.z], 1)] = s.z;
        g_csr[atomicAdd(&g_cursor[d.w], 1)] = s.w;
    }
}

__device__ __forceinline__ void gemm1_body(const float* __restrict__ x,
                                           const float* __restrict__ W1,
                                           int N, int vbid) {
    extern __shared__ float sm[];
    float* Ws = sm;                    // [128][32]
    float* xs = sm + 128 * 32;         // [64][132] padded

    int t = threadIdx.x;
    int nodebase = vbid * G1_NODES;

    {
        const float4* w4 = (const float4*)W1;
        float4* ws4 = (float4*)Ws;
        for (int i = t; i < 1024; i += 256) ws4[i] = w4[i];
    }
    for (int idx = t; idx < G1_NODES * 32; idx += 256) {
        int node = idx >> 5;
        int f4 = idx & 31;
        float4 v = make_float4(0.f, 0.f, 0.f, 0.f);
        int n = nodebase + node;
        if (n < N) v = *(const float4*)(x + (size_t)n * 128 + f4 * 4);
        *(float4*)(xs + node * G1_XPITCH + f4 * 4) = v;
    }
    __syncthreads();

    int c0 = (t & 7) * 4;
    int r0 = (t >> 3) * 2;
    float acc[2][4];
#pragma unroll
    for (int j = 0; j < 2; j++)
#pragma unroll
        for (int c = 0; c < 4; c++) acc[j][c] = 0.f;

#pragma unroll 4
    for (int k0 = 0; k0 < 128; k0 += 4) {
        float4 xr[2], w[4];
#pragma unroll
        for (int j = 0; j < 2; j++) xr[j] = *(float4*)(xs + (r0 + j) * G1_XPITCH + k0);
#pragma unroll
        for (int i = 0; i < 4; i++) w[i] = *(float4*)(Ws + (k0 + i) * 32 + c0);
#pragma unroll
        for (int j = 0; j < 2; j++) {
            acc[j][0] = fmaf(xr[j].x, w[0].x, acc[j][0]);
            acc[j][1] = fmaf(xr[j].x, w[0].y, acc[j][1]);
            acc[j][2] = fmaf(xr[j].x, w[0].z, acc[j][2]);
            acc[j][3] = fmaf(xr[j].x, w[0].w, acc[j][3]);
            acc[j][0] = fmaf(xr[j].y, w[1].x, acc[j][0]);
            acc[j][1] = fmaf(xr[j].y, w[1].y, acc[j][1]);
            acc[j][2] = fmaf(xr[j].y, w[1].z, acc[j][2]);
            acc[j][3] = fmaf(xr[j].y, w[1].w, acc[j][3]);
            acc[j][0] = fmaf(xr[j].z, w[2].x, acc[j][0]);
            acc[j][1] = fmaf(xr[j].z, w[2].y, acc[j][1]);
            acc[j][2] = fmaf(xr[j].z, w[2].z, acc[j][2]);
            acc[j][3] = fmaf(xr[j].z, w[2].w, acc[j][3]);
            acc[j][0] = fmaf(xr[j].w, w[3].x, acc[j][0]);
            acc[j][1] = fmaf(xr[j].w, w[3].y, acc[j][1]);
            acc[j][2] = fmaf(xr[j].w, w[3].z, acc[j][2]);
            acc[j][3] = fmaf(xr[j].w, w[3].w, acc[j][3]);
        }
    }

#pragma unroll
    for (int j = 0; j < 2; j++) {
        int n = nodebase + r0 + j;
        if (n < N) {
            float di = g_dinv[n];
            float4 o = make_float4(acc[j][0] * di, acc[j][1] * di, acc[j][2] * di, acc[j][3] * di);
            *(float4*)(g_h1s + (size_t)n * 32 + c0) = o;
        }
    }
}

// role interleave: even bids (first 2*SBLK) scatter, odd gemm; tail = gemm
__global__ void __launch_bounds__(256) k_fused(const int* __restrict__ ei, int E,
                                               const float* __restrict__ x,
                                               const float* __restrict__ W1, int N) {
    int bid = blockIdx.x;
    if (bid < 2 * SBLK) {
        if (bid & 1) gemm1_body(x, W1, N, bid >> 1);
        else         scatter_body(ei, E, bid >> 1);
    } else {
        gemm1_body(x, W1, N, SBLK + (bid - 2 * SBLK));
    }
}

// ---------------- shared gather helper: sum rows tbl[s*32+lane] over a CSR range ----------------
__device__ __forceinline__ float csr_row_sum(const float* __restrict__ tbl,
                                             int r0, int r1, int lane, float acc) {
    for (int base = r0; base < r1; base += 32) {
        int rem = r1 - base;
        int cnt = rem < 32 ? rem : 32;
        int idx = (lane < cnt) ? __ldg(&g_csr[base + lane]) : 0;
        int i = 0;
        for (; i + 8 <= cnt; i += 8) {
            int s0 = __shfl_sync(0xffffffffu, idx, i);
            int s1 = __shfl_sync(0xffffffffu, idx, i + 1);
            int s2 = __shfl_sync(0xffffffffu, idx, i + 2);
            int s3 = __shfl_sync(0xffffffffu, idx, i + 3);
            int s4 = __shfl_sync(0xffffffffu, idx, i + 4);
            int s5 = __shfl_sync(0xffffffffu, idx, i + 5);
            int s6 = __shfl_sync(0xffffffffu, idx, i + 6);
            int s7 = __shfl_sync(0xffffffffu, idx, i + 7);
            float v0 = __ldg(&tbl[s0 * 32 + lane]);
            float v1 = __ldg(&tbl[s1 * 32 + lane]);
            float v2 = __ldg(&tbl[s2 * 32 + lane]);
            float v3 = __ldg(&tbl[s3 * 32 + lane]);
            float v4 = __ldg(&tbl[s4 * 32 + lane]);
            float v5 = __ldg(&tbl[s5 * 32 + lane]);
            float v6 = __ldg(&tbl[s6 * 32 + lane]);
            float v7 = __ldg(&tbl[s7 * 32 + lane]);
            acc += ((v0 + v1) + (v2 + v3)) + ((v4 + v5) + (v6 + v7));
        }
        for (; i < cnt; i++) {
            int s = __shfl_sync(0xffffffffu, idx, i);
            acc += __ldg(&tbl[s * 32 + lane]);
        }
    }
    return acc;
}

// ---------------- agg layer 1 + relu + fused GEMM2 ----------------
__global__ void __launch_bounds__(256) k_agg1g2(const float* __restrict__ b1,
                                                const float* __restrict__ W2, int N) {
    __shared__ float W2s[32 * 32];
    for (int i = threadIdx.x; i < 32 * 32; i += blockDim.x) {
        int k = i >> 5, c = i & 31;
        W2s[i] = (c < NC) ? W2[k * NC + c] : 0.f;
    }
    __syncthreads();
    int lane = threadIdx.x & 31;
    int warp = (blockIdx.x * blockDim.x + threadIdx.x) >> 5;
    int nwarps = (gridDim.x * blockDim.x) >> 5;
    float bias = b1[lane];
    int chunk = (N + nwarps - 1) / nwarps;
    int n0 = warp * chunk;
    int n1 = min(N, n0 + chunk);
    for (int n = n0; n < n1; n++) {
        int r0 = g_rowstart[n], r1 = g_rowstart[n + 1];
        float acc = csr_row_sum(g_h1s, r0, r1, lane, g_h1s[n * 32 + lane]);
        float di = g_dinv[n];
        float hv = fmaxf(di * acc + bias, 0.f);
        float z = 0.f;
#pragma unroll
        for (int k = 0; k < 32; k++)
            z = fmaf(__shfl_sync(0xffffffffu, hv, k), W2s[k * 32 + lane], z);
        g_zs[n * 32 + lane] = (lane < NC) ? z * di : 0.f;
    }
}

// ---------------- agg layer 2 + bias + softmax + column log-sums + bf16 FX ----------------
__global__ void __launch_bounds__(256) k_agg2(const float* __restrict__ b2,
                                              float* __restrict__ out, int N) {
    __shared__ float scs[32];
    int lane = threadIdx.x & 31;
    if (threadIdx.x < 32) scs[threadIdx.x] = 0.f;
    __syncthreads();
    int warp = (blockIdx.x * blockDim.x + threadIdx.x) >> 5;
    int nwarps = (gridDim.x * blockDim.x) >> 5;
    float bias = (lane < NC) ? b2[lane] : 0.f;
    float nfacc = 0.f;
    int chunk = (N + nwarps - 1) / nwarps;
    int n0 = warp * chunk;
    int n1 = min(N, n0 + chunk);
    for (int n = n0; n < n1; n++) {
        int r0 = g_rowstart[n], r1 = g_rowstart[n + 1];
        float acc = csr_row_sum(g_zs, r0, r1, lane, g_zs[n * 32 + lane]);
        float logit = (lane < NC) ? (g_dinv[n] * acc + bias) : -1e30f;
        float m = logit;
#pragma unroll
        for (int o = 16; o > 0; o >>= 1) m = fmaxf(m, __shfl_xor_sync(0xffffffffu, m, o));
        float p = (lane < NC) ? expf(logit - m) : 0.f;
        float s = p;
#pragma unroll
        for (int o = 16; o > 0; o >>= 1) s += __shfl_xor_sync(0xffffffffu, s, o);
        float fx = p / s;
        float fxhi = __shfl_down_sync(0xffffffffu, fx, 1);
        if ((lane & 1) == 0)
            g_fxh[n * 16 + (lane >> 1)] = __floats2bfloat162_rn(fx, fxhi);
        if (lane < NC) {
            out[(size_t)n * NC + lane] = fx;
            nfacc += logf(1.f - fx * fx);
        }
    }
    atomicAdd(&scs[lane], nfacc);
    __syncthreads();
    if (threadIdx.x < 32) {
        float v = scs[threadIdx.x];
        if (v != 0.f) atomicAdd(&g_colsum[threadIdx.x], (double)v);
    }
}

// ---------------- FF: 8 lanes per edge (4 edges/warp), unroll x2 ----------------
__global__ void __launch_bounds__(256) k_ff(const int* __restrict__ ei,
                                            const float* __restrict__ ep, int E) {
    __shared__ float red[256];
    int lane = threadIdx.x & 31;
    int grp = lane >> 3;     // 0..3
    int l8 = lane & 7;       // 0..7
    int warp = (blockIdx.x * blockDim.x + threadIdx.x) >> 5;
    int nwarps = (gridDim.x * blockDim.x) >> 5;
    float acc = 0.f;
    for (int base = warp * 8; base < E; base += nwarps * 8) {
#pragma unroll
        for (int u = 0; u < 2; u++) {
            int e = base + u * 4 + grp;
            bool valid = (e < E);
            int ec = valid ? e : 0;
            int s = __ldg(&ei[ec]);
            int d = __ldg(&ei[E + ec]);
            float pl = valid ? __ldg(&ep[ec]) : 0.f;
            uint2 ar = *(const uint2*)(g_fxh + s * 16 + l8 * 2);
            uint2 br = *(const uint2*)(g_fxh + d * 16 + l8 * 2);
            float2 a0 = __bfloat1622float2(*(__nv_bfloat162*)&ar.x);
            float2 a1 = __bfloat1622float2(*(__nv_bfloat162*)&ar.y);
            float2 b0 = __bfloat1622float2(*(__nv_bfloat162*)&br.x);
            float2 b1 = __bfloat1622float2(*(__nv_bfloat162*)&br.y);
            float v = a0.x * b0.x;
            v = fmaf(a0.y, b0.y, v);
            v = fmaf(a1.x, b1.x, v);
            v = fmaf(a1.y, b1.y, v);
#pragma unroll
            for (int o = 1; o <= 4; o <<= 1) v += __shfl_xor_sync(0xffffffffu, v, o);
            if (l8 == 0 && valid) {
                float df = v - pl;
                acc += df * df;
            }
        }
    }
    red[threadIdx.x] = acc;
    __syncthreads();
    for (int off = 128; off > 0; off >>= 1) {
        if (threadIdx.x < off) red[threadIdx.x] += red[threadIdx.x + off];
        __syncthreads();
    }
    if (threadIdx.x == 0) atomicAdd(&g_mse, (double)red[0]);
}

// ---------------- final loss ----------------
__global__ void k_finish(float* __restrict__ out, int N, int E) {
    if (threadIdx.x == 0 && blockIdx.x == 0) {
        double preg = 0.0;
        for (int c = 0; c < NC; c++) {
            double S = g_colsum[c];
            preg -= log(1.0001 - exp(S));
        }
        double loss = g_mse / (double)E + 0.01 * preg;
        out[(size_t)N * NC] = (float)loss;
    }
}

// ---------------- launch ----------------
extern "C" void kernel_launch(void* const* d_in, const int* in_sizes, int n_in,
                              void* d_out, int out_size) {
    const float* x  = (const float*)d_in[0];
    const int*   ei = (const int*)d_in[1];
    const float* ep = (const float*)d_in[2];
    const float* W1 = (const float*)d_in[3];
    const float* b1 = (const float*)d_in[4];
    const float* W2 = (const float*)d_in[5];
    const float* b2 = (const float*)d_in[6];
    float* out = (float*)d_out;

    int N = in_sizes[0] / 128;   // 100000
    int E = in_sizes[2];         // 3200000
    int NB = (N + 1023) / 1024;  // 98

    // Idempotent, stream-free setup (no static guards).
    cudaFuncSetAttribute(k_fused, cudaFuncAttributeMaxDynamicSharedMemorySize, G1_SMEM);
    void* cnt_ptr = nullptr;
    cudaGetSymbolAddress(&cnt_ptr, g_cnt);

    int gemm_blocks = (N + G1_NODES - 1) / G1_NODES;   // 1563
    int fused_blocks = SBLK + gemm_blocks;             // 2747

    cudaMemsetAsync(cnt_ptr, 0, (size_t)N * sizeof(int), 0);
    k_hist<<<1024, 256>>>(ei, E);                                   // launch 0
    k_scan1<<<NB, 1024>>>(N);                                       // launch 1
    k_scan3<<<NB, 1024>>>(N);                                       // launch 2
    k_fused<<<fused_blocks, 256, G1_SMEM>>>(ei, E, x, W1, N);       // launch 3 (profiled)
    k_agg1g2<<<1184, 256>>>(b1, W2, N);                             // launch 4
    k_agg2<<<1184, 256>>>(b2, out, N);                              // launch 5
    k_ff<<<1184, 256>>>(ei, ep, E);                                 // launch 6
    k_finish<<<1, 32>>>(out, N, E);                                 // launch 7
}

// round 12
// speedup vs baseline: 1.6398x; 1.1569x over previous
#include <cuda_runtime.h>
#include <cuda_bf16.h>
#include <cuda_fp16.h>
#include <math.h>

#define NMAX 100000
#define EMAX 3200000
#define NC   30
#define CAP  128           // fixed CSR capacity per node (Poisson(32): P(deg>=128) ~ 1e-40)

// ---------------- scratch ----------------
__device__ int    g_cnt[NMAX];             // per-dst cursor == in-degree after scatter
__device__ int    g_csrf[NMAX * CAP];      // fixed-stride CSR (src lists)
__device__ float  g_dinv[NMAX];
__device__ float  g_h1f[NMAX * 32];        // unscaled x @ W1 (fp32, written by gemm1)
__device__ __half g_h1h[NMAX * 32];        // dinv[n] * (x@W1)[n,:] in fp16 (gather table)
__device__ __half g_zsh[NMAX * 32];        // dinv[n] * (relu @ W2) in fp16, padded
__device__ __nv_bfloat162 g_fxh[NMAX * 16];// FX rows in bf16 (for k_ff)
__device__ double g_colsum[32];
__device__ double g_mse;

// ---------------- fused: direct scatter + GEMM1 (independent work) ----------------
#define G1_NODES 64
#define G1_XPITCH 132
#define G1_SMEM ((128 * 32 + G1_NODES * G1_XPITCH) * 4)
#define SBLK 1184

__device__ __forceinline__ void scatter_body(const int* __restrict__ ei, int E, int vbid) {
    int i = vbid * 256 + threadIdx.x;
    int stride = SBLK * 256;
    int nv = E >> 2;
    const int4* s4p = (const int4*)ei;
    const int4* d4p = (const int4*)(ei + E);
    for (int v = i; v < nv; v += stride) {
        int4 s = s4p[v];
        int4 d = d4p[v];
        int p0 = atomicAdd(&g_cnt[d.x], 1);
        int p1 = atomicAdd(&g_cnt[d.y], 1);
        int p2 = atomicAdd(&g_cnt[d.z], 1);
        int p3 = atomicAdd(&g_cnt[d.w], 1);
        if (p0 < CAP) g_csrf[d.x * CAP + p0] = s.x;
        if (p1 < CAP) g_csrf[d.y * CAP + p1] = s.y;
        if (p2 < CAP) g_csrf[d.z * CAP + p2] = s.z;
        if (p3 < CAP) g_csrf[d.w * CAP + p3] = s.w;
    }
}

__device__ __forceinline__ void gemm1_body(const float* __restrict__ x,
                                           const float* __restrict__ W1,
                                           int N, int vbid) {
    extern __shared__ float sm[];
    float* Ws = sm;                    // [128][32]
    float* xs = sm + 128 * 32;         // [64][132] padded

    int t = threadIdx.x;
    int nodebase = vbid * G1_NODES;

    {
        const float4* w4 = (const float4*)W1;
        float4* ws4 = (float4*)Ws;
        for (int i = t; i < 1024; i += 256) ws4[i] = w4[i];
    }
    for (int idx = t; idx < G1_NODES * 32; idx += 256) {
        int node = idx >> 5;
        int f4 = idx & 31;
        float4 v = make_float4(0.f, 0.f, 0.f, 0.f);
        int n = nodebase + node;
        if (n < N) v = *(const float4*)(x + (size_t)n * 128 + f4 * 4);
        *(float4*)(xs + node * G1_XPITCH + f4 * 4) = v;
    }
    __syncthreads();

    int c0 = (t & 7) * 4;
    int r0 = (t >> 3) * 2;
    float acc[2][4];
#pragma unroll
    for (int j = 0; j < 2; j++)
#pragma unroll
        for (int c = 0; c < 4; c++) acc[j][c] = 0.f;

#pragma unroll 4
    for (int k0 = 0; k0 < 128; k0 += 4) {
        float4 xr[2], w[4];
#pragma unroll
        for (int j = 0; j < 2; j++) xr[j] = *(float4*)(xs + (r0 + j) * G1_XPITCH + k0);
#pragma unroll
        for (int i = 0; i < 4; i++) w[i] = *(float4*)(Ws + (k0 + i) * 32 + c0);
#pragma unroll
        for (int j = 0; j < 2; j++) {
            acc[j][0] = fmaf(xr[j].x, w[0].x, acc[j][0]);
            acc[j][1] = fmaf(xr[j].x, w[0].y, acc[j][1]);
            acc[j][2] = fmaf(xr[j].x, w[0].z, acc[j][2]);
            acc[j][3] = fmaf(xr[j].x, w[0].w, acc[j][3]);
            acc[j][0] = fmaf(xr[j].y, w[1].x, acc[j][0]);
            acc[j][1] = fmaf(xr[j].y, w[1].y, acc[j][1]);
            acc[j][2] = fmaf(xr[j].y, w[1].z, acc[j][2]);
            acc[j][3] = fmaf(xr[j].y, w[1].w, acc[j][3]);
            acc[j][0] = fmaf(xr[j].z, w[2].x, acc[j][0]);
            acc[j][1] = fmaf(xr[j].z, w[2].y, acc[j][1]);
            acc[j][2] = fmaf(xr[j].z, w[2].z, acc[j][2]);
            acc[j][3] = fmaf(xr[j].z, w[2].w, acc[j][3]);
            acc[j][0] = fmaf(xr[j].w, w[3].x, acc[j][0]);
            acc[j][1] = fmaf(xr[j].w, w[3].y, acc[j][1]);
            acc[j][2] = fmaf(xr[j].w, w[3].z, acc[j][2]);
            acc[j][3] = fmaf(xr[j].w, w[3].w, acc[j][3]);
        }
    }

#pragma unroll
    for (int j = 0; j < 2; j++) {
        int n = nodebase + r0 + j;
        if (n < N) {
            float4 o = make_float4(acc[j][0], acc[j][1], acc[j][2], acc[j][3]);
            *(float4*)(g_h1f + (size_t)n * 32 + c0) = o;   // unscaled
        }
    }
}

__global__ void __launch_bounds__(256) k_fused(const int* __restrict__ ei, int E,
                                               const float* __restrict__ x,
                                               const float* __restrict__ W1, int N) {
    int bid = blockIdx.x;
    if (bid < 2 * SBLK) {
        if (bid & 1) gemm1_body(x, W1, N, bid >> 1);
        else         scatter_body(ei, E, bid >> 1);
    } else {
        gemm1_body(x, W1, N, SBLK + (bid - 2 * SBLK));
    }
}

// ---------------- scale: dinv from counts; h1h = fp16(dinv * h1f); zero loss accs ----------------
__global__ void __launch_bounds__(256) k_scale(int N) {
    int idx = blockIdx.x * blockDim.x + threadIdx.x;
    if (blockIdx.x == 0) {
        if (threadIdx.x < 32) g_colsum[threadIdx.x] = 0.0;
        if (threadIdx.x == 0) g_mse = 0.0;
    }
    if (idx >= N * 32) return;
    int n = idx >> 5;
    int cnt = g_cnt[n];
    float di = rsqrtf((float)(cnt + 1));   // deg = in-degree + self-loop
    if ((idx & 31) == 0) g_dinv[n] = di;
    g_h1h[idx] = __float2half(di * g_h1f[idx]);
}

// ---------------- gather helper: fp16 rows via fixed-stride CSR ----------------
__device__ __forceinline__ float csr_row_sum_h(const __half* __restrict__ tbl,
                                               int n, int cnt, int lane, float acc) {
    const int* __restrict__ row = g_csrf + n * CAP;
    if (cnt > CAP) cnt = CAP;
    for (int base = 0; base < cnt; base += 32) {
        int c = cnt - base;
        if (c > 32) c = 32;
        int idx = (lane < c) ? __ldg(&row[base + lane]) : 0;
        int i = 0;
        for (; i + 8 <= c; i += 8) {
            int s0 = __shfl_sync(0xffffffffu, idx, i);
            int s1 = __shfl_sync(0xffffffffu, idx, i + 1);
            int s2 = __shfl_sync(0xffffffffu, idx, i + 2);
            int s3 = __shfl_sync(0xffffffffu, idx, i + 3);
            int s4 = __shfl_sync(0xffffffffu, idx, i + 4);
            int s5 = __shfl_sync(0xffffffffu, idx, i + 5);
            int s6 = __shfl_sync(0xffffffffu, idx, i + 6);
            int s7 = __shfl_sync(0xffffffffu, idx, i + 7);
            float v0 = __half2float(__ldg(&tbl[s0 * 32 + lane]));
            float v1 = __half2float(__ldg(&tbl[s1 * 32 + lane]));
            float v2 = __half2float(__ldg(&tbl[s2 * 32 + lane]));
            float v3 = __half2float(__ldg(&tbl[s3 * 32 + lane]));
            float v4 = __half2float(__ldg(&tbl[s4 * 32 + lane]));
            float v5 = __half2float(__ldg(&tbl[s5 * 32 + lane]));
            float v6 = __half2float(__ldg(&tbl[s6 * 32 + lane]));
            float v7 = __half2float(__ldg(&tbl[s7 * 32 + lane]));
            acc += ((v0 + v1) + (v2 + v3)) + ((v4 + v5) + (v6 + v7));
        }
        for (; i < c; i++) {
            int s = __shfl_sync(0xffffffffu, idx, i);
            acc += __half2float(__ldg(&tbl[s * 32 + lane]));
        }
    }
    return acc;
}

// ---------------- agg layer 1 + relu + fused GEMM2 ----------------
__global__ void __launch_bounds__(256) k_agg1g2(const float* __restrict__ b1,
                                                const float* __restrict__ W2, int N) {
    __shared__ float W2s[32 * 32];
    for (int i = threadIdx.x; i < 32 * 32; i += blockDim.x) {
        int k = i >> 5, c = i & 31;
        W2s[i] = (c < NC) ? W2[k * NC + c] : 0.f;
    }
    __syncthreads();
    int lane = threadIdx.x & 31;
    int warp = (blockIdx.x * blockDim.x + threadIdx.x) >> 5;
    int nwarps = (gridDim.x * blockDim.x) >> 5;
    float bias = b1[lane];
    int chunk = (N + nwarps - 1) / nwarps;
    int n0 = warp * chunk;
    int n1 = min(N, n0 + chunk);
    for (int n = n0; n < n1; n++) {
        int cnt = g_cnt[n];
        float self = __half2float(g_h1h[n * 32 + lane]);
        float acc = csr_row_sum_h(g_h1h, n, cnt, lane, self);
        float di = g_dinv[n];
        float hv = fmaxf(di * acc + bias, 0.f);
        float z = 0.f;
#pragma unroll
        for (int k = 0; k < 32; k++)
            z = fmaf(__shfl_sync(0xffffffffu, hv, k), W2s[k * 32 + lane], z);
        g_zsh[n * 32 + lane] = __float2half((lane < NC) ? z * di : 0.f);
    }
}

// ---------------- agg layer 2 + bias + softmax + column log-sums + bf16 FX ----------------
__global__ void __launch_bounds__(256) k_agg2(const float* __restrict__ b2,
                                              float* __restrict__ out, int N) {
    __shared__ float scs[32];
    int lane = threadIdx.x & 31;
    if (threadIdx.x < 32) scs[threadIdx.x] = 0.f;
    __syncthreads();
    int warp = (blockIdx.x * blockDim.x + threadIdx.x) >> 5;
    int nwarps = (gridDim.x * blockDim.x) >> 5;
    float bias = (lane < NC) ? b2[lane] : 0.f;
    float nfacc = 0.f;
    int chunk = (N + nwarps - 1) / nwarps;
    int n0 = warp * chunk;
    int n1 = min(N, n0 + chunk);
    for (int n = n0; n < n1; n++) {
        int cnt = g_cnt[n];
        float self = __half2float(g_zsh[n * 32 + lane]);
        float acc = csr_row_sum_h(g_zsh, n, cnt, lane, self);
        float logit = (lane < NC) ? (g_dinv[n] * acc + bias) : -1e30f;
        float m = logit;
#pragma unroll
        for (int o = 16; o > 0; o >>= 1) m = fmaxf(m, __shfl_xor_sync(0xffffffffu, m, o));
        float p = (lane < NC) ? expf(logit - m) : 0.f;
        float s = p;
#pragma unroll
        for (int o = 16; o > 0; o >>= 1) s += __shfl_xor_sync(0xffffffffu, s, o);
        float fx = p / s;
        float fxhi = __shfl_down_sync(0xffffffffu, fx, 1);
        if ((lane & 1) == 0)
            g_fxh[n * 16 + (lane >> 1)] = __floats2bfloat162_rn(fx, fxhi);
        if (lane < NC) {
            out[(size_t)n * NC + lane] = fx;
            nfacc += logf(1.f - fx * fx);
        }
    }
    atomicAdd(&scs[lane], nfacc);
    __syncthreads();
    if (threadIdx.x < 32) {
        float v = scs[threadIdx.x];
        if (v != 0.f) atomicAdd(&g_colsum[threadIdx.x], (double)v);
    }
}

// ---------------- FF: 8 lanes per edge (4 edges/warp), unroll x2 ----------------
__global__ void __launch_bounds__(256) k_ff(const int* __restrict__ ei,
                                            const float* __restrict__ ep, int E) {
    __shared__ float red[256];
    int lane = threadIdx.x & 31;
    int grp = lane >> 3;
    int l8 = lane & 7;
    int warp = (blockIdx.x * blockDim.x + threadIdx.x) >> 5;
    int nwarps = (gridDim.x * blockDim.x) >> 5;
    float acc = 0.f;
    for (int base = warp * 8; base < E; base += nwarps * 8) {
#pragma unroll
        for (int u = 0; u < 2; u++) {
            int e = base + u * 4 + grp;
            bool valid = (e < E);
            int ec = valid ? e : 0;
            int s = __ldg(&ei[ec]);
            int d = __ldg(&ei[E + ec]);
            float pl = valid ? __ldg(&ep[ec]) : 0.f;
            uint2 ar = *(const uint2*)(g_fxh + s * 16 + l8 * 2);
            uint2 br = *(const uint2*)(g_fxh + d * 16 + l8 * 2);
            float2 a0 = __bfloat1622float2(*(__nv_bfloat162*)&ar.x);
            float2 a1 = __bfloat1622float2(*(__nv_bfloat162*)&ar.y);
            float2 b0 = __bfloat1622float2(*(__nv_bfloat162*)&br.x);
            float2 b1 = __bfloat1622float2(*(__nv_bfloat162*)&br.y);
            float v = a0.x * b0.x;
            v = fmaf(a0.y, b0.y, v);
            v = fmaf(a1.x, b1.x, v);
            v = fmaf(a1.y, b1.y, v);
#pragma unroll
            for (int o = 1; o <= 4; o <<= 1) v += __shfl_xor_sync(0xffffffffu, v, o);
            if (l8 == 0 && valid) {
                float df = v - pl;
                acc += df * df;
            }
        }
    }
    red[threadIdx.x] = acc;
    __syncthreads();
    for (int off = 128; off > 0; off >>= 1) {
        if (threadIdx.x < off) red[threadIdx.x] += red[threadIdx.x + off];
        __syncthreads();
    }
    if (threadIdx.x == 0) atomicAdd(&g_mse, (double)red[0]);
}

// ---------------- final loss (warp-parallel preg) ----------------
__global__ void k_finish(float* __restrict__ out, int N, int E) {
    int lane = threadIdx.x & 31;
    double term = 0.0;
    if (lane < NC) {
        double S = g_colsum[lane];
        term = -log(1.0001 - exp(S));
    }
#pragma unroll
    for (int o = 16; o > 0; o >>= 1) term += __shfl_xor_sync(0xffffffffu, term, o);
    if (lane == 0) {
        double loss = g_mse / (double)E + 0.01 * term;
        out[(size_t)N * NC] = (float)loss;
    }
}

// ---------------- launch ----------------
extern "C" void kernel_launch(void* const* d_in, const int* in_sizes, int n_in,
                              void* d_out, int out_size) {
    const float* x  = (const float*)d_in[0];
    const int*   ei = (const int*)d_in[1];
    const float* ep = (const float*)d_in[2];
    const float* W1 = (const float*)d_in[3];
    const float* b1 = (const float*)d_in[4];
    const float* W2 = (const float*)d_in[5];
    const float* b2 = (const float*)d_in[6];
    float* out = (float*)d_out;

    int N = in_sizes[0] / 128;   // 100000
    int E = in_sizes[2];         // 3200000

    // Idempotent, stream-free setup (no static guards).
    cudaFuncSetAttribute(k_fused, cudaFuncAttributeMaxDynamicSharedMemorySize, G1_SMEM);
    void* cnt_ptr = nullptr;
    cudaGetSymbolAddress(&cnt_ptr, g_cnt);

    int gemm_blocks = (N + G1_NODES - 1) / G1_NODES;   // 1563
    int fused_blocks = SBLK + gemm_blocks;

    cudaMemsetAsync(cnt_ptr, 0, (size_t)N * sizeof(int), 0);
    k_fused<<<fused_blocks, 256, G1_SMEM>>>(ei, E, x, W1, N);       // kernel 0
    k_scale<<<(N * 32 + 255) / 256, 256>>>(N);                      // kernel 1
    k_agg1g2<<<1184, 256>>>(b1, W2, N);                             // kernel 2
    k_agg2<<<1184, 256>>>(b2, out, N);                              // kernel 3 (profiled)
    k_ff<<<1184, 256>>>(ei, ep, E);                                 // kernel 4
    k_finish<<<1, 32>>>(out, N, E);                                 // kernel 5
}

// round 13
// speedup vs baseline: 1.8290x; 1.1154x over previous
#include <cuda_runtime.h>
#include <cuda_bf16.h>
#include <cuda_fp16.h>
#include <math.h>

#define NMAX 100000
#define EMAX 3200000
#define NC   30
#define CAP  128           // fixed CSR capacity per node (Poisson(32): P(deg>=128) ~ 1e-40)

// ---------------- scratch ----------------
__device__ int    g_cnt[NMAX];             // per-dst cursor == in-degree after scatter
__device__ int    g_csrf[NMAX * CAP];      // fixed-stride CSR (src lists)
__device__ float  g_dinv[NMAX];
__device__ float  g_h1f[NMAX * 32];        // unscaled x @ W1 (fp32, written by gemm1)
__device__ __half g_h1h[NMAX * 32];        // dinv[n] * (x@W1)[n,:] in fp16 (gather table)
__device__ __half g_zsh[NMAX * 32];        // dinv[n] * (relu @ W2) in fp16, padded
__device__ __nv_bfloat162 g_fxh[NMAX * 16];// FX rows in bf16 (for k_ff)
__device__ double g_colsum[32];
__device__ double g_mse;

// ---------------- fused: direct scatter + GEMM1 (independent work) ----------------
#define G1_NODES 64
#define G1_XPITCH 132
#define G1_SMEM ((128 * 32 + G1_NODES * G1_XPITCH) * 4)
#define SBLK 1184

__device__ __forceinline__ void scatter_body(const int* __restrict__ ei, int E, int vbid) {
    int i = vbid * 256 + threadIdx.x;
    int stride = SBLK * 256;
    int nv = E >> 2;
    const int4* s4p = (const int4*)ei;
    const int4* d4p = (const int4*)(ei + E);
    for (int v = i; v < nv; v += stride) {
        int4 s = s4p[v];
        int4 d = d4p[v];
        int p0 = atomicAdd(&g_cnt[d.x], 1);
        int p1 = atomicAdd(&g_cnt[d.y], 1);
        int p2 = atomicAdd(&g_cnt[d.z], 1);
        int p3 = atomicAdd(&g_cnt[d.w], 1);
        if (p0 < CAP) g_csrf[d.x * CAP + p0] = s.x;
        if (p1 < CAP) g_csrf[d.y * CAP + p1] = s.y;
        if (p2 < CAP) g_csrf[d.z * CAP + p2] = s.z;
        if (p3 < CAP) g_csrf[d.w * CAP + p3] = s.w;
    }
}

__device__ __forceinline__ void gemm1_body(const float* __restrict__ x,
                                           const float* __restrict__ W1,
                                           int N, int vbid) {
    extern __shared__ float sm[];
    float* Ws = sm;                    // [128][32]
    float* xs = sm + 128 * 32;         // [64][132] padded

    int t = threadIdx.x;
    int nodebase = vbid * G1_NODES;

    {
        const float4* w4 = (const float4*)W1;
        float4* ws4 = (float4*)Ws;
        for (int i = t; i < 1024; i += 256) ws4[i] = w4[i];
    }
    for (int idx = t; idx < G1_NODES * 32; idx += 256) {
        int node = idx >> 5;
        int f4 = idx & 31;
        float4 v = make_float4(0.f, 0.f, 0.f, 0.f);
        int n = nodebase + node;
        if (n < N) v = *(const float4*)(x + (size_t)n * 128 + f4 * 4);
        *(float4*)(xs + node * G1_XPITCH + f4 * 4) = v;
    }
    __syncthreads();

    int c0 = (t & 7) * 4;
    int r0 = (t >> 3) * 2;
    float acc[2][4];
#pragma unroll
    for (int j = 0; j < 2; j++)
#pragma unroll
        for (int c = 0; c < 4; c++) acc[j][c] = 0.f;

#pragma unroll 4
    for (int k0 = 0; k0 < 128; k0 += 4) {
        float4 xr[2], w[4];
#pragma unroll
        for (int j = 0; j < 2; j++) xr[j] = *(float4*)(xs + (r0 + j) * G1_XPITCH + k0);
#pragma unroll
        for (int i = 0; i < 4; i++) w[i] = *(float4*)(Ws + (k0 + i) * 32 + c0);
#pragma unroll
        for (int j = 0; j < 2; j++) {
            acc[j][0] = fmaf(xr[j].x, w[0].x, acc[j][0]);
            acc[j][1] = fmaf(xr[j].x, w[0].y, acc[j][1]);
            acc[j][2] = fmaf(xr[j].x, w[0].z, acc[j][2]);
            acc[j][3] = fmaf(xr[j].x, w[0].w, acc[j][3]);
            acc[j][0] = fmaf(xr[j].y, w[1].x, acc[j][0]);
            acc[j][1] = fmaf(xr[j].y, w[1].y, acc[j][1]);
            acc[j][2] = fmaf(xr[j].y, w[1].z, acc[j][2]);
            acc[j][3] = fmaf(xr[j].y, w[1].w, acc[j][3]);
            acc[j][0] = fmaf(xr[j].z, w[2].x, acc[j][0]);
            acc[j][1] = fmaf(xr[j].z, w[2].y, acc[j][1]);
            acc[j][2] = fmaf(xr[j].z, w[2].z, acc[j][2]);
            acc[j][3] = fmaf(xr[j].z, w[2].w, acc[j][3]);
            acc[j][0] = fmaf(xr[j].w, w[3].x, acc[j][0]);
            acc[j][1] = fmaf(xr[j].w, w[3].y, acc[j][1]);
            acc[j][2] = fmaf(xr[j].w, w[3].z, acc[j][2]);
            acc[j][3] = fmaf(xr[j].w, w[3].w, acc[j][3]);
        }
    }

#pragma unroll
    for (int j = 0; j < 2; j++) {
        int n = nodebase + r0 + j;
        if (n < N) {
            float4 o = make_float4(acc[j][0], acc[j][1], acc[j][2], acc[j][3]);
            *(float4*)(g_h1f + (size_t)n * 32 + c0) = o;   // unscaled
        }
    }
}

__global__ void __launch_bounds__(256) k_fused(const int* __restrict__ ei, int E,
                                               const float* __restrict__ x,
                                               const float* __restrict__ W1, int N) {
    int bid = blockIdx.x;
    if (bid < 2 * SBLK) {
        if (bid & 1) gemm1_body(x, W1, N, bid >> 1);
        else         scatter_body(ei, E, bid >> 1);
    } else {
        gemm1_body(x, W1, N, SBLK + (bid - 2 * SBLK));
    }
}

// ---------------- scale: dinv from counts; h1h = fp16(dinv * h1f); zero loss accs ----------------
__global__ void __launch_bounds__(256) k_scale(int N) {
    int idx = blockIdx.x * blockDim.x + threadIdx.x;
    if (blockIdx.x == 0) {
        if (threadIdx.x < 32) g_colsum[threadIdx.x] = 0.0;
        if (threadIdx.x == 0) g_mse = 0.0;
    }
    if (idx >= N * 32) return;
    int n = idx >> 5;
    int cnt = g_cnt[n];
    float di = rsqrtf((float)(cnt + 1));   // deg = in-degree + self-loop
    if ((idx & 31) == 0) g_dinv[n] = di;
    g_h1h[idx] = __float2half(di * g_h1f[idx]);
}

// ---------------- dual-edge half2 gather: two 16-lane halves, one LDG.32/lane ----------------
// Returns the per-lane (32-wide feature layout) neighbor sum for node n.
__device__ __forceinline__ float csr_row_sum_h2(const __half* __restrict__ tbl,
                                                int n, int cnt, int lane) {
    const int* __restrict__ row = g_csrf + n * CAP;
    if (cnt > CAP) cnt = CAP;
    const __half2* __restrict__ t2 = (const __half2*)tbl;
    int l16 = lane & 15;
    int hi = lane >> 4;          // which edge of the pair this half handles
    float ax = 0.f, ay = 0.f;
    for (int base = 0; base < cnt; base += 32) {
        int c = cnt - base;
        if (c > 32) c = 32;
        int idx = (lane < c) ? __ldg(&row[base + lane]) : 0;
        int i = 0;
        for (; i + 8 <= c; i += 8) {
            int s0 = __shfl_sync(0xffffffffu, idx, i + hi);
            int s1 = __shfl_sync(0xffffffffu, idx, i + 2 + hi);
            int s2 = __shfl_sync(0xffffffffu, idx, i + 4 + hi);
            int s3 = __shfl_sync(0xffffffffu, idx, i + 6 + hi);
            __half2 h0 = __ldg(&t2[s0 * 16 + l16]);
            __half2 h1 = __ldg(&t2[s1 * 16 + l16]);
            __half2 h2 = __ldg(&t2[s2 * 16 + l16]);
            __half2 h3 = __ldg(&t2[s3 * 16 + l16]);
            float2 f0 = __half22float2(h0);
            float2 f1 = __half22float2(h1);
            float2 f2 = __half22float2(h2);
            float2 f3 = __half22float2(h3);
            ax += (f0.x + f1.x) + (f2.x + f3.x);
            ay += (f0.y + f1.y) + (f2.y + f3.y);
        }
        for (; i < c; i += 2) {
            int e = i + hi;
            bool valid = (e < c);
            int s = __shfl_sync(0xffffffffu, idx, valid ? e : 0);
            __half2 h = __ldg(&t2[s * 16 + l16]);
            float2 f = __half22float2(h);
            if (valid) { ax += f.x; ay += f.y; }
        }
    }
    // merge halves (both processed disjoint edge subsets of the same node)
    ax += __shfl_xor_sync(0xffffffffu, ax, 16);
    ay += __shfl_xor_sync(0xffffffffu, ay, 16);
    // redistribute: feature f (=lane) lives in lane f>>1, component f&1
    float vx = __shfl_sync(0xffffffffu, ax, lane >> 1);
    float vy = __shfl_sync(0xffffffffu, ay, lane >> 1);
    return (lane & 1) ? vy : vx;
}

// ---------------- agg layer 1 + relu + fused GEMM2 ----------------
__global__ void __launch_bounds__(256) k_agg1g2(const float* __restrict__ b1,
                                                const float* __restrict__ W2, int N) {
    __shared__ float W2s[32 * 32];
    for (int i = threadIdx.x; i < 32 * 32; i += blockDim.x) {
        int k = i >> 5, c = i & 31;
        W2s[i] = (c < NC) ? W2[k * NC + c] : 0.f;
    }
    __syncthreads();
    int lane = threadIdx.x & 31;
    int warp = (blockIdx.x * blockDim.x + threadIdx.x) >> 5;
    int nwarps = (gridDim.x * blockDim.x) >> 5;
    float bias = b1[lane];
    int chunk = (N + nwarps - 1) / nwarps;
    int n0 = warp * chunk;
    int n1 = min(N, n0 + chunk);
    for (int n = n0; n < n1; n++) {
        int cnt = g_cnt[n];
        float self = __half2float(g_h1h[n * 32 + lane]);
        float acc = self + csr_row_sum_h2(g_h1h, n, cnt, lane);
        float di = g_dinv[n];
        float hv = fmaxf(di * acc + bias, 0.f);
        float z = 0.f;
#pragma unroll
        for (int k = 0; k < 32; k++)
            z = fmaf(__shfl_sync(0xffffffffu, hv, k), W2s[k * 32 + lane], z);
        g_zsh[n * 32 + lane] = __float2half((lane < NC) ? z * di : 0.f);
    }
}

// ---------------- agg layer 2 + bias + softmax + column log-sums + bf16 FX ----------------
__global__ void __launch_bounds__(256) k_agg2(const float* __restrict__ b2,
                                              float* __restrict__ out, int N) {
    __shared__ float scs[32];
    int lane = threadIdx.x & 31;
    if (threadIdx.x < 32) scs[threadIdx.x] = 0.f;
    __syncthreads();
    int warp = (blockIdx.x * blockDim.x + threadIdx.x) >> 5;
    int nwarps = (gridDim.x * blockDim.x) >> 5;
    float bias = (lane < NC) ? b2[lane] : 0.f;
    float nfacc = 0.f;
    int chunk = (N + nwarps - 1) / nwarps;
    int n0 = warp * chunk;
    int n1 = min(N, n0 + chunk);
    for (int n = n0; n < n1; n++) {
        int cnt = g_cnt[n];
        float self = __half2float(g_zsh[n * 32 + lane]);
        float acc = self + csr_row_sum_h2(g_zsh, n, cnt, lane);
        float logit = (lane < NC) ? (g_dinv[n] * acc + bias) : -1e30f;
        float m = logit;
#pragma unroll
        for (int o = 16; o > 0; o >>= 1) m = fmaxf(m, __shfl_xor_sync(0xffffffffu, m, o));
        float p = (lane < NC) ? __expf(logit - m) : 0.f;
        float s = p;
#pragma unroll
        for (int o = 16; o > 0; o >>= 1) s += __shfl_xor_sync(0xffffffffu, s, o);
        float fx = p / s;
        float fxhi = __shfl_down_sync(0xffffffffu, fx, 1);
        if ((lane & 1) == 0)
            g_fxh[n * 16 + (lane >> 1)] = __floats2bfloat162_rn(fx, fxhi);
        if (lane < NC) {
            out[(size_t)n * NC + lane] = fx;
            nfacc += __logf(1.f - fx * fx);
        }
    }
    atomicAdd(&scs[lane], nfacc);
    __syncthreads();
    if (threadIdx.x < 32) {
        float v = scs[threadIdx.x];
        if (v != 0.f) atomicAdd(&g_colsum[threadIdx.x], (double)v);
    }
}

// ---------------- FF: 8 lanes per edge (4 edges/warp), unroll x2 ----------------
__global__ void __launch_bounds__(256) k_ff(const int* __restrict__ ei,
                                            const float* __restrict__ ep, int E) {
    __shared__ float red[256];
    int lane = threadIdx.x & 31;
    int grp = lane >> 3;
    int l8 = lane & 7;
    int warp = (blockIdx.x * blockDim.x + threadIdx.x) >> 5;
    int nwarps = (gridDim.x * blockDim.x) >> 5;
    float acc = 0.f;
    for (int base = warp * 8; base < E; base += nwarps * 8) {
#pragma unroll
        for (int u = 0; u < 2; u++) {
            int e = base + u * 4 + grp;
            bool valid = (e < E);
            int ec = valid ? e : 0;
            int s = __ldg(&ei[ec]);
            int d = __ldg(&ei[E + ec]);
            float pl = valid ? __ldg(&ep[ec]) : 0.f;
            uint2 ar = *(const uint2*)(g_fxh + s * 16 + l8 * 2);
            uint2 br = *(const uint2*)(g_fxh + d * 16 + l8 * 2);
            float2 a0 = __bfloat1622float2(*(__nv_bfloat162*)&ar.x);
            float2 a1 = __bfloat1622float2(*(__nv_bfloat162*)&ar.y);
            float2 b0 = __bfloat1622float2(*(__nv_bfloat162*)&br.x);
            float2 b1 = __bfloat1622float2(*(__nv_bfloat162*)&br.y);
            float v = a0.x * b0.x;
            v = fmaf(a0.y, b0.y, v);
            v = fmaf(a1.x, b1.x, v);
            v = fmaf(a1.y, b1.y, v);
#pragma unroll
            for (int o = 1; o <= 4; o <<= 1) v += __shfl_xor_sync(0xffffffffu, v, o);
            if (l8 == 0 && valid) {
                float df = v - pl;
                acc += df * df;
            }
        }
    }
    red[threadIdx.x] = acc;
    __syncthreads();
    for (int off = 128; off > 0; off >>= 1) {
        if (threadIdx.x < off) red[threadIdx.x] += red[threadIdx.x + off];
        __syncthreads();
    }
    if (threadIdx.x == 0) atomicAdd(&g_mse, (double)red[0]);
}

// ---------------- final loss (warp-parallel preg) ----------------
__global__ void k_finish(float* __restrict__ out, int N, int E) {
    int lane = threadIdx.x & 31;
    double term = 0.0;
    if (lane < NC) {
        double S = g_colsum[lane];
        term = -log(1.0001 - exp(S));
    }
#pragma unroll
    for (int o = 16; o > 0; o >>= 1) term += __shfl_xor_sync(0xffffffffu, term, o);
    if (lane == 0) {
        double loss = g_mse / (double)E + 0.01 * term;
        out[(size_t)N * NC] = (float)loss;
    }
}

// ---------------- launch ----------------
extern "C" void kernel_launch(void* const* d_in, const int* in_sizes, int n_in,
                              void* d_out, int out_size) {
    const float* x  = (const float*)d_in[0];
    const int*   ei = (const int*)d_in[1];
    const float* ep = (const float*)d_in[2];
    const float* W1 = (const float*)d_in[3];
    const float* b1 = (const float*)d_in[4];
    const float* W2 = (const float*)d_in[5];
    const float* b2 = (const float*)d_in[6];
    float* out = (float*)d_out;

    int N = in_sizes[0] / 128;   // 100000
    int E = in_sizes[2];         // 3200000

    // Idempotent, stream-free setup (no static guards).
    cudaFuncSetAttribute(k_fused, cudaFuncAttributeMaxDynamicSharedMemorySize, G1_SMEM);
    void* cnt_ptr = nullptr;
    cudaGetSymbolAddress(&cnt_ptr, g_cnt);

    int gemm_blocks = (N + G1_NODES - 1) / G1_NODES;   // 1563
    int fused_blocks = SBLK + gemm_blocks;

    cudaMemsetAsync(cnt_ptr, 0, (size_t)N * sizeof(int), 0);
    k_fused<<<fused_blocks, 256, G1_SMEM>>>(ei, E, x, W1, N);       // kernel 0
    k_scale<<<(N * 32 + 255) / 256, 256>>>(N);                      // kernel 1
    k_agg1g2<<<1184, 256>>>(b1, W2, N);                             // kernel 2
    k_agg2<<<1184, 256>>>(b2, out, N);                              // kernel 3 (profiled)
    k_ff<<<1184, 256>>>(ei, ep, E);                                 // kernel 4
    k_finish<<<1, 32>>>(out, N, E);                                 // kernel 5
}